// round 3
// baseline (speedup 1.0000x reference)
#include <cuda_runtime.h>
#include <math.h>

#define BB 8
#define TT 32
#define CC 1024
#define HH 128
#define DST 32
#define FIN 64
#define SS 27            // T - INIT_LENGTH - 1
#define ROWS (BB*CC)     // 8192

// ---------------- device scratch (allocation-free contract) ----------------
__device__ float g_Lf[(size_t)TT*CC*CC];     // 134 MB
__device__ float g_Lb[(size_t)TT*CC*CC];     // 134 MB
__device__ float g_X [(size_t)BB*TT*CC*FIN]; // 64 MB  (gathered x)
__device__ float g_h [ROWS*HH];
__device__ float g_Zf[ROWS*192];
__device__ float g_Zb[ROWS*192];
__device__ float g_xh[ROWS*192];             // [tmp(64) | hs(128)]
__device__ float g_gcat[ROWS*256];
__device__ float g_gi[ROWS*384];
__device__ float g_gh[ROWS*384];
__device__ float g_pred[ROWS*DST];
__device__ float g_dinvf[TT*CC];
__device__ float g_dinvb[TT*CC];
__device__ int   g_mask[CC];

// ---------------- prolog kernels ----------------
__global__ void rowsum_kernel(const float* __restrict__ adj){
    int warp = (blockIdx.x*blockDim.x + threadIdx.x) >> 5;
    int lane = threadIdx.x & 31;
    if (warp >= TT*CC) return;
    const float* row = adj + (size_t)warp*CC;
    float s = 0.f;
    for (int j = lane; j < CC; j += 32) s += row[j];
    #pragma unroll
    for (int o = 16; o; o >>= 1) s += __shfl_xor_sync(0xffffffffu, s, o);
    if (!lane) g_dinvf[warp] = 1.0f / sqrtf(s + 1.0f);
}

__global__ void colsum_kernel(const float* __restrict__ adj){
    int t = blockIdx.y;
    int i = blockIdx.x*blockDim.x + threadIdx.x; // 0..1023
    const float* base = adj + (size_t)t*CC*CC + i;
    float s = 0.f;
    for (int j = 0; j < CC; j++) s += base[(size_t)j*CC];
    g_dinvb[t*CC + i] = 1.0f / sqrtf(s + 1.0f);
}

// Lf[t][i][j] = (adj[t][i][j] + d_ij) * df[i]*df[j]
// Lb[t][j][i] = (adj[t][i][j] + d_ij) * db[i]*db[j]   (transpose via smem)
__global__ void build_L_kernel(const float* __restrict__ adj){
    __shared__ float tile[32][33];
    int t = blockIdx.z;
    int i0 = blockIdx.y*32, j0 = blockIdx.x*32;
    int tx = threadIdx.x, ty = threadIdx.y; // (32,8)
    const float* df = g_dinvf + t*CC;
    const float* db = g_dinvb + t*CC;
    #pragma unroll
    for (int r = 0; r < 4; r++){
        int li = ty + r*8;
        int i = i0 + li, j = j0 + tx;
        float v = adj[((size_t)t*CC + i)*CC + j] + ((i == j) ? 1.f : 0.f);
        g_Lf[((size_t)t*CC + i)*CC + j] = v * df[i] * df[j];
        tile[li][tx] = v * db[i] * db[j];
    }
    __syncthreads();
    #pragma unroll
    for (int r = 0; r < 4; r++){
        int lj = ty + r*8;
        int p = j0 + lj, q = i0 + tx;
        g_Lb[((size_t)t*CC + p)*CC + q] = tile[tx][lj];
    }
}

// x = concat(inputs[...,:32], inputs[...,128:160])  -> g_X (B,T,C,64)
__global__ void build_X_kernel(const float* __restrict__ in){
    size_t idx = (size_t)blockIdx.x*blockDim.x + threadIdx.x; // float4 index
    if (idx >= (size_t)BB*TT*CC*16) return;
    int q = (int)(idx & 15);
    size_t row = idx >> 4;
    int srccol = (q < 8) ? q*4 : 96 + q*4;
    float4 v = *(const float4*)(in + row*160 + srccol);
    ((float4*)g_X)[idx] = v;
}

__global__ void mask_init_kernel(){
    int i = blockIdx.x*blockDim.x + threadIdx.x;
    if (i < CC) g_mask[i] = 0;
}
__global__ void mask_set_kernel(const int* __restrict__ cells, int n){
    int i = blockIdx.x*blockDim.x + threadIdx.x;
    if (i < n) g_mask[cells[i]] = 1;
}

// ---------------- propagation GEMM: Z[dir][b] = L[dir][t] @ [x_t | h] ----------------
// grid: x = n-tile (n0 = 64*x, n<64 -> X, else h), y = m-tile (128), z = dir*8+batch
__global__ void __launch_bounds__(256) prop_gemm_kernel(int t, int two_dirs){
    int z = blockIdx.z;
    int dir, batch;
    if (two_dirs){ dir = z >> 3; batch = z & 7; } else { dir = 0; batch = z; }
    const float* Lsrc = (dir == 0 ? g_Lf : g_Lb) + (size_t)t*CC*CC;
    float* Zdst = (dir == 0 ? g_Zf : g_Zb);
    int n0 = blockIdx.x * 64;
    int m0 = blockIdx.y * 128;
    const float* Bsrc; int ldb;
    if (n0 == 0){ Bsrc = g_X + ((size_t)(batch*TT + t)*CC)*FIN; ldb = FIN; }
    else        { Bsrc = g_h + (size_t)batch*CC*HH + (n0 - 64); ldb = HH; }

    __shared__ float As[16][132];
    __shared__ float Bs[16][68];

    int tid = threadIdx.x;
    int tx = tid & 15, ty = tid >> 4;
    int arow = tid >> 2, acol = (tid & 3) << 2;
    int brow = tid >> 4, bcol = (tid & 15) << 2;

    float acc[8][4];
    #pragma unroll
    for (int i = 0; i < 8; i++)
        #pragma unroll
        for (int j = 0; j < 4; j++) acc[i][j] = 0.f;

    for (int k0 = 0; k0 < CC; k0 += 16){
        float4 a0 = *(const float4*)(Lsrc + (size_t)(m0 + arow     )*CC + k0 + acol);
        float4 a1 = *(const float4*)(Lsrc + (size_t)(m0 + arow + 64)*CC + k0 + acol);
        As[acol+0][arow] = a0.x; As[acol+1][arow] = a0.y;
        As[acol+2][arow] = a0.z; As[acol+3][arow] = a0.w;
        As[acol+0][arow+64] = a1.x; As[acol+1][arow+64] = a1.y;
        As[acol+2][arow+64] = a1.z; As[acol+3][arow+64] = a1.w;
        float4 bv = *(const float4*)(Bsrc + (size_t)(k0 + brow)*ldb + bcol);
        *(float4*)&Bs[brow][bcol] = bv;
        __syncthreads();
        #pragma unroll
        for (int kk = 0; kk < 16; kk++){
            float4 aA = *(const float4*)&As[kk][ty*8];
            float4 aB = *(const float4*)&As[kk][ty*8 + 4];
            float4 bV = *(const float4*)&Bs[kk][tx*4];
            float av[8] = {aA.x,aA.y,aA.z,aA.w,aB.x,aB.y,aB.z,aB.w};
            float bw[4] = {bV.x,bV.y,bV.z,bV.w};
            #pragma unroll
            for (int i = 0; i < 8; i++)
                #pragma unroll
                for (int j = 0; j < 4; j++) acc[i][j] += av[i]*bw[j];
        }
        __syncthreads();
    }
    float* cbase = Zdst + ((size_t)batch*CC + m0)*192 + n0;
    #pragma unroll
    for (int i = 0; i < 8; i++){
        float4 o = make_float4(acc[i][0], acc[i][1], acc[i][2], acc[i][3]);
        *(float4*)(cbase + (size_t)(ty*8 + i)*192 + tx*4) = o;
    }
}

// ---------------- generic small GEMM: C = act(A@B + bias), M = 8192 ----------------
template<int ACT>
__global__ void __launch_bounds__(256)
gemm_kernel(const float* __restrict__ A, int lda,
            const float* __restrict__ Bm, int ldb,
            const float* __restrict__ bias,
            float* __restrict__ C, int ldc,
            int N, int K)
{
    __shared__ float As[16][132];
    __shared__ float Bs[16][68];
    int m0 = blockIdx.y * 128;
    int n0 = blockIdx.x * 64;
    int tid = threadIdx.x;
    int tx = tid & 15, ty = tid >> 4;
    int arow = tid >> 2, acol = (tid & 3) << 2;
    int brow = tid >> 4, bcol = (tid & 15) << 2;

    float acc[8][4];
    #pragma unroll
    for (int i = 0; i < 8; i++)
        #pragma unroll
        for (int j = 0; j < 4; j++) acc[i][j] = 0.f;

    for (int k0 = 0; k0 < K; k0 += 16){
        float4 a0 = *(const float4*)(A + (size_t)(m0 + arow     )*lda + k0 + acol);
        float4 a1 = *(const float4*)(A + (size_t)(m0 + arow + 64)*lda + k0 + acol);
        As[acol+0][arow] = a0.x; As[acol+1][arow] = a0.y;
        As[acol+2][arow] = a0.z; As[acol+3][arow] = a0.w;
        As[acol+0][arow+64] = a1.x; As[acol+1][arow+64] = a1.y;
        As[acol+2][arow+64] = a1.z; As[acol+3][arow+64] = a1.w;
        float4 bv = make_float4(0.f,0.f,0.f,0.f);
        if (n0 + bcol < N)
            bv = *(const float4*)(Bm + (size_t)(k0 + brow)*ldb + n0 + bcol);
        *(float4*)&Bs[brow][bcol] = bv;
        __syncthreads();
        #pragma unroll
        for (int kk = 0; kk < 16; kk++){
            float4 aA = *(const float4*)&As[kk][ty*8];
            float4 aB = *(const float4*)&As[kk][ty*8 + 4];
            float4 bV = *(const float4*)&Bs[kk][tx*4];
            float av[8] = {aA.x,aA.y,aA.z,aA.w,aB.x,aB.y,aB.z,aB.w};
            float bw[4] = {bV.x,bV.y,bV.z,bV.w};
            #pragma unroll
            for (int i = 0; i < 8; i++)
                #pragma unroll
                for (int j = 0; j < 4; j++) acc[i][j] += av[i]*bw[j];
        }
        __syncthreads();
    }
    int cn = n0 + tx*4;
    if (cn < N){
        float4 bb = *(const float4*)(bias + cn);
        #pragma unroll
        for (int i = 0; i < 8; i++){
            float4 o;
            o.x = acc[i][0] + bb.x;
            o.y = acc[i][1] + bb.y;
            o.z = acc[i][2] + bb.z;
            o.w = acc[i][3] + bb.w;
            if (ACT){
                o.x = fmaxf(o.x, 0.f); o.y = fmaxf(o.y, 0.f);
                o.z = fmaxf(o.z, 0.f); o.w = fmaxf(o.w, 0.f);
            }
            *(float4*)(C + (size_t)(m0 + ty*8 + i)*ldc + cn) = o;
        }
    }
}

// ---------------- GRU gates (h_new = (1-z)*n + z*hs; note: blends with hs!) ----------------
__global__ void gru_gate_kernel(){
    int idx = blockIdx.x*blockDim.x + threadIdx.x; // ROWS*HH
    int r = idx >> 7, f = idx & 127;
    const float* gi = g_gi + (size_t)r*384;
    const float* gh = g_gh + (size_t)r*384;
    float ir = gi[f], iz = gi[128 + f], inn = gi[256 + f];
    float hr = gh[f], hz = gh[128 + f], hn  = gh[256 + f];
    float rg = 1.f / (1.f + expf(-(ir + hr)));
    float zg = 1.f / (1.f + expf(-(iz + hz)));
    float ng = tanhf(inn + rg*hn);
    float hs = g_xh[(size_t)r*192 + 64 + f];   // reference gru() receives hs as its "h"
    g_h[idx] = (1.f - zg)*ng + zg*hs;
}

// ---------------- output scatter: pred for ~mask, raw input for mask ----------------
__global__ void output_kernel(const float* __restrict__ in, float* __restrict__ out, int t){
    int idx = blockIdx.x*blockDim.x + threadIdx.x; // B*C*8 float4s
    if (idx >= BB*CC*8) return;
    int q = idx & 7;
    int c = (idx >> 3) & (CC - 1);
    int b = idx >> 13;
    float4 v;
    if (g_mask[c])
        v = *(const float4*)(in + (((size_t)(b*TT + t + 1)*CC + c)*160) + q*4);
    else
        v = *(const float4*)(g_pred + ((size_t)(b*CC + c)*DST) + q*4);
    *(float4*)(out + (((size_t)(b*SS + (t - 4))*CC + c)*DST) + q*4) = v;
}

// ---------------- host orchestration ----------------
static float* symf(const void* s){ void* p = nullptr; cudaGetSymbolAddress(&p, s); return (float*)p; }

extern "C" void kernel_launch(void* const* d_in, const int* in_sizes, int n_in,
                              void* d_out, int out_size)
{
    const float* inputs   = (const float*)d_in[0];
    const float* adj      = (const float*)d_in[1];
    const float* init_W   = (const float*)d_in[2];
    const float* init_b   = (const float*)d_in[3];
    const float* fe_fwd_W = (const float*)d_in[4];
    const float* fe_fwd_b = (const float*)d_in[5];
    const float* fe_bwd_W = (const float*)d_in[6];
    const float* fe_bwd_b = (const float*)d_in[7];
    const float* fwd_W    = (const float*)d_in[8];
    const float* fwd_b    = (const float*)d_in[9];
    const float* bwd_W    = (const float*)d_in[10];
    const float* bwd_b    = (const float*)d_in[11];
    const float* merge_W  = (const float*)d_in[12];
    const float* merge_b  = (const float*)d_in[13];
    const float* gru_Wih  = (const float*)d_in[14];
    const float* gru_bih  = (const float*)d_in[15];
    const float* gru_Whh  = (const float*)d_in[16];
    const float* gru_bhh  = (const float*)d_in[17];
    const float* out_W    = (const float*)d_in[18];
    const float* out_b    = (const float*)d_in[19];
    const int*   cells    = (const int*)  d_in[20];
    float* out = (float*)d_out;

    float* pZf   = symf(g_Zf);
    float* pZb   = symf(g_Zb);
    float* pxh   = symf(g_xh);
    float* pgcat = symf(g_gcat);
    float* pgi   = symf(g_gi);
    float* pgh   = symf(g_gh);
    float* ph    = symf(g_h);
    float* ppred = symf(g_pred);

    // ---- prolog ----
    rowsum_kernel<<<TT*CC/8, 256>>>(adj);
    colsum_kernel<<<dim3(4, TT), 256>>>(adj);
    build_L_kernel<<<dim3(CC/32, CC/32, TT), dim3(32, 8)>>>(adj);
    build_X_kernel<<<(BB*TT*CC*16)/256, 256>>>(inputs);
    mask_init_kernel<<<4, 256>>>();
    int nic = in_sizes[20];
    mask_set_kernel<<<(nic + 255)/256, 256>>>(cells, nic);

    // hidden0 = relu(Lf[0] @ x0 @ init_W + init_b)
    prop_gemm_kernel<<<dim3(1, 8, 8), 256>>>(0, 0);                       // Zf[:,:,:64]
    gemm_kernel<1><<<dim3(2, 64), 256>>>(pZf, 192, init_W, HH, init_b,
                                         ph, HH, HH, FIN);

    // ---- scan ----
    for (int t = 0; t < TT - 1; t++){
        // Zf/Zb = L @ [x_t | h]
        prop_gemm_kernel<<<dim3(3, 8, 16), 256>>>(t, 1);

        // fe = relu(Z[:, :64] @ feW + b) -> xh[:, 0:64]
        gemm_kernel<1><<<dim3(1, 64), 256>>>(pZf, 192, fe_fwd_W, DST, fe_fwd_b,
                                             pxh + 0, 192, DST, FIN);
        gemm_kernel<1><<<dim3(1, 64), 256>>>(pZb, 192, fe_bwd_W, DST, fe_bwd_b,
                                             pxh + 32, 192, DST, FIN);
        // gcn = relu(Z[:, 64:192] @ {fwd,bwd}_W + b) -> gcat
        gemm_kernel<1><<<dim3(2, 64), 256>>>(pZf + 64, 192, fwd_W, HH, fwd_b,
                                             pgcat + 0, 256, HH, HH);
        gemm_kernel<1><<<dim3(2, 64), 256>>>(pZb + 64, 192, bwd_W, HH, bwd_b,
                                             pgcat + 128, 256, HH, HH);
        // hs = gcat @ merge_W + merge_b -> xh[:, 64:192]
        gemm_kernel<0><<<dim3(2, 64), 256>>>(pgcat, 256, merge_W, HH, merge_b,
                                             pxh + 64, 192, HH, 256);
        // gi = tmp @ Wih + bih ; gh = hs @ Whh + bhh
        gemm_kernel<0><<<dim3(6, 64), 256>>>(pxh + 0, 192, gru_Wih, 384, gru_bih,
                                             pgi, 384, 384, FIN);
        gemm_kernel<0><<<dim3(6, 64), 256>>>(pxh + 64, 192, gru_Whh, 384, gru_bhh,
                                             pgh, 384, 384, HH);
        // h = gru(...)
        gru_gate_kernel<<<(ROWS*HH)/256, 256>>>();

        if (t >= 4){
            gemm_kernel<0><<<dim3(1, 64), 256>>>(ph, HH, out_W, DST, out_b,
                                                 ppred, DST, DST, HH);
            output_kernel<<<(BB*CC*8)/256, 256>>>(inputs, out, t);
        }
    }
}

// round 5
// speedup vs baseline: 1.5624x; 1.5624x over previous
#include <cuda_runtime.h>
#include <cuda_bf16.h>
#include <math.h>

#define BB 8
#define TT 32
#define CC 1024
#define HH 128
#define DST 32
#define FIN 64
#define SS 27            // T - INIT_LENGTH - 1
#define ROWS (BB*CC)     // 8192

// ================= warp-MMA helpers (sm_80-class, compiles on plain sm_103) ==========
__device__ __forceinline__ unsigned smem_u32(const void* p){
    unsigned a;
    asm("{ .reg .u64 t; cvta.to.shared.u64 t, %1; cvt.u32.u64 %0, t; }" : "=r"(a) : "l"(p));
    return a;
}

__device__ __forceinline__ void ldsm4(unsigned& r0, unsigned& r1, unsigned& r2, unsigned& r3,
                                      unsigned addr){
    asm volatile("ldmatrix.sync.aligned.m8n8.x4.shared.b16 {%0,%1,%2,%3}, [%4];"
                 : "=r"(r0), "=r"(r1), "=r"(r2), "=r"(r3) : "r"(addr));
}

__device__ __forceinline__ void mma16816(float* c, const unsigned* a, unsigned b0, unsigned b1){
    asm volatile("mma.sync.aligned.m16n8k16.row.col.f32.bf16.bf16.f32 "
                 "{%0,%1,%2,%3}, {%4,%5,%6,%7}, {%8,%9}, {%0,%1,%2,%3};"
                 : "+f"(c[0]), "+f"(c[1]), "+f"(c[2]), "+f"(c[3])
                 : "r"(a[0]), "r"(a[1]), "r"(a[2]), "r"(a[3]), "r"(b0), "r"(b1));
}

__device__ __forceinline__ void cp16(unsigned dst, const void* src){
    asm volatile("cp.async.cg.shared.global [%0], [%1], 16;"
                 :: "r"(dst), "l"(__cvta_generic_to_global(src)));
}

// ---------------- device scratch (allocation-free contract) ----------------
__device__ __nv_bfloat16 g_LfHi[(size_t)TT*CC*CC];
__device__ __nv_bfloat16 g_LfLo[(size_t)TT*CC*CC];
__device__ __nv_bfloat16 g_LbHi[(size_t)TT*CC*CC];
__device__ __nv_bfloat16 g_LbLo[(size_t)TT*CC*CC];
__device__ __nv_bfloat16 g_BXhi[(size_t)BB*TT*FIN*CC];  // [b][t][f][c]
__device__ __nv_bfloat16 g_BXlo[(size_t)BB*TT*FIN*CC];
__device__ __nv_bfloat16 g_BHhi[(size_t)BB*HH*CC];      // [b][f][c]
__device__ __nv_bfloat16 g_BHlo[(size_t)BB*HH*CC];
__device__ float g_h [ROWS*HH];
__device__ float g_Zf[ROWS*192];
__device__ float g_Zb[ROWS*192];
__device__ float g_xh[ROWS*192];             // [tmp(64) | hs(128)]
__device__ float g_gcat[ROWS*256];
__device__ float g_gi[ROWS*384];
__device__ float g_gh[ROWS*384];
__device__ float g_pred[ROWS*DST];
__device__ float g_dinvf[TT*CC];
__device__ float g_dinvb[TT*CC];
__device__ int   g_mask[CC];

// ---------------- prolog kernels ----------------
__global__ void rowsum_kernel(const float* __restrict__ adj){
    int warp = (blockIdx.x*blockDim.x + threadIdx.x) >> 5;
    int lane = threadIdx.x & 31;
    if (warp >= TT*CC) return;
    const float* row = adj + (size_t)warp*CC;
    float s = 0.f;
    for (int j = lane; j < CC; j += 32) s += row[j];
    #pragma unroll
    for (int o = 16; o; o >>= 1) s += __shfl_xor_sync(0xffffffffu, s, o);
    if (!lane) g_dinvf[warp] = 1.0f / sqrtf(s + 1.0f);
}

__global__ void colsum_kernel(const float* __restrict__ adj){
    int t = blockIdx.y;
    int i = blockIdx.x*blockDim.x + threadIdx.x;
    const float* base = adj + (size_t)t*CC*CC + i;
    float s = 0.f;
    for (int j = 0; j < CC; j++) s += base[(size_t)j*CC];
    g_dinvb[t*CC + i] = 1.0f / sqrtf(s + 1.0f);
}

__device__ __forceinline__ void split_bf16(float v, __nv_bfloat16& hi, __nv_bfloat16& lo){
    hi = __float2bfloat16(v);
    lo = __float2bfloat16(v - __bfloat162float(hi));
}

// Lf[t][i][j], Lb[t][j][i] as bf16 hi/lo
__global__ void build_L_kernel(const float* __restrict__ adj){
    __shared__ float tile[32][33];
    int t = blockIdx.z;
    int i0 = blockIdx.y*32, j0 = blockIdx.x*32;
    int tx = threadIdx.x, ty = threadIdx.y; // (32,8)
    const float* df = g_dinvf + t*CC;
    const float* db = g_dinvb + t*CC;
    #pragma unroll
    for (int r = 0; r < 4; r++){
        int li = ty + r*8;
        int i = i0 + li, j = j0 + tx;
        float v = adj[((size_t)t*CC + i)*CC + j] + ((i == j) ? 1.f : 0.f);
        float vf = v * df[i] * df[j];
        __nv_bfloat16 h1, l1;
        split_bf16(vf, h1, l1);
        size_t off = ((size_t)t*CC + i)*CC + j;
        g_LfHi[off] = h1; g_LfLo[off] = l1;
        tile[li][tx] = v * db[i] * db[j];
    }
    __syncthreads();
    #pragma unroll
    for (int r = 0; r < 4; r++){
        int lj = ty + r*8;
        int p = j0 + lj, q = i0 + tx;
        __nv_bfloat16 h1, l1;
        split_bf16(tile[tx][lj], h1, l1);
        size_t off = ((size_t)t*CC + p)*CC + q;
        g_LbHi[off] = h1; g_LbLo[off] = l1;
    }
}

// BX[b][t][f][c] = x[b][t][c][f] (gathered feats), transposed + bf16 split
__global__ void build_BX_kernel(const float* __restrict__ in){
    __shared__ float tile[32][33];
    int c0 = blockIdx.x*32, f0 = blockIdx.y*32;
    int bt = blockIdx.z;                    // b*32+t
    int tx = threadIdx.x, ty = threadIdx.y; // (32,8)
    #pragma unroll
    for (int r = 0; r < 4; r++){
        int c = c0 + ty + r*8;
        int f = f0 + tx;
        int col = (f < 32) ? f : 96 + f;
        tile[ty + r*8][tx] = in[(((size_t)bt*CC) + c)*160 + col];
    }
    __syncthreads();
    #pragma unroll
    for (int r = 0; r < 4; r++){
        int f = f0 + ty + r*8;
        int c = c0 + tx;
        __nv_bfloat16 h1, l1;
        split_bf16(tile[tx][ty + r*8], h1, l1);
        size_t off = (((size_t)bt*FIN) + f)*CC + c;
        g_BXhi[off] = h1; g_BXlo[off] = l1;
    }
}

// BH[b][f][c] = h[b][c][f] transposed + split
__global__ void transpose_h_kernel(){
    __shared__ float tile[32][33];
    int c0 = blockIdx.x*32, f0 = blockIdx.y*32;
    int b = blockIdx.z;
    int tx = threadIdx.x, ty = threadIdx.y;
    #pragma unroll
    for (int r = 0; r < 4; r++){
        int c = c0 + ty + r*8;
        int f = f0 + tx;
        tile[ty + r*8][tx] = g_h[((size_t)b*CC + c)*HH + f];
    }
    __syncthreads();
    #pragma unroll
    for (int r = 0; r < 4; r++){
        int f = f0 + ty + r*8;
        int c = c0 + tx;
        __nv_bfloat16 h1, l1;
        split_bf16(tile[tx][ty + r*8], h1, l1);
        size_t off = ((size_t)b*HH + f)*CC + c;
        g_BHhi[off] = h1; g_BHlo[off] = l1;
    }
}

__global__ void zero_BH_kernel(){
    int i = blockIdx.x*blockDim.x + threadIdx.x;
    if (i < BB*HH*CC/2){
        ((unsigned*)g_BHhi)[i] = 0;
        ((unsigned*)g_BHlo)[i] = 0;
    }
}

__global__ void mask_init_kernel(){
    int i = blockIdx.x*blockDim.x + threadIdx.x;
    if (i < CC) g_mask[i] = 0;
}
__global__ void mask_set_kernel(const int* __restrict__ cells, int n){
    int i = blockIdx.x*blockDim.x + threadIdx.x;
    if (i < n) g_mask[cells[i]] = 1;
}

// ================ HMMA propagation: Z[dir][b] = L[dir][t] @ [x_t | h] ================
// grid (b=8, mtile=16); mtile>>3 = dir, (mtile&7)*128 = row block. Per CTA:
// C tile M=128 x N=192, K=1024 in 16 stages of 64.
// bf16 split: D += Ahi*Bhi + Ahi*Blo + Alo*Bhi, fp32 accum in registers.
// smem stage: Ahi(16KB) Alo(16KB) Bhi(24KB) Blo(24KB), SW128-swizzled 128B rows.
#define PROP_HDR   1024
#define PROP_BUFSZ 81920
#define PROP_SMEM  (PROP_HDR + 2*PROP_BUFSZ)

__device__ __forceinline__ void prop_load_stage(int s, int buf, int b, int t, int mtile,
                                                unsigned smem_base, int tid){
    int k0 = s*64;
    unsigned base = smem_base + PROP_HDR + buf*PROP_BUFSZ;
    int dir = mtile >> 3;
    #pragma unroll
    for (int it = 0; it < 20; it++){
        int idx = tid + it*256;
        const __nv_bfloat16* src;
        unsigned sec;
        int row, col, arr;
        if (idx < 2048){
            arr = idx >> 10; int rc = idx & 1023; row = rc >> 3; col = rc & 7;
            const __nv_bfloat16* Lp = dir ? (arr ? g_LbLo : g_LbHi)
                                          : (arr ? g_LfLo : g_LfHi);
            src = Lp + (((size_t)t*CC) + ((mtile & 7)*128 + row))*CC + k0 + col*8;
            sec = arr * 16384u;
        } else {
            int ib = idx - 2048;
            arr = (ib >= 1536); int rc = ib - arr*1536; row = rc >> 3; col = rc & 7;
            if (row < 64){
                const __nv_bfloat16* Xp = arr ? g_BXlo : g_BXhi;
                src = Xp + (((size_t)(b*TT + t)*FIN) + row)*CC + k0 + col*8;
            } else {
                const __nv_bfloat16* Hp = arr ? g_BHlo : g_BHhi;
                src = Hp + (((size_t)b*HH) + (row - 64))*CC + k0 + col*8;
            }
            sec = 32768u + arr*24576u;
        }
        unsigned boff = row*128 + col*16;
        unsigned sw = boff ^ ((boff >> 3) & 0x70);
        cp16(base + sec + sw, src);
    }
}

__global__ void __launch_bounds__(256) prop_mma_kernel(int t){
    extern __shared__ char smem[];
    unsigned smem_base = smem_u32(smem);
    int tid = threadIdx.x;
    int b = blockIdx.x;
    int mtile = blockIdx.y;
    int dir = mtile >> 3;

    int wid = tid >> 5;
    int lane = tid & 31;
    int m0 = (wid >> 1) * 32;   // warp m-offset within 128
    int n0 = (wid & 1) * 96;    // warp n-offset within 192
    int lrow = lane & 7;
    int lq8  = (lane >> 3) & 1;
    int lkhi = lane >> 4;

    float acc[2][6][2][4];
    #pragma unroll
    for (int mi = 0; mi < 2; mi++)
        #pragma unroll
        for (int nc = 0; nc < 6; nc++)
            #pragma unroll
            for (int sb = 0; sb < 2; sb++)
                #pragma unroll
                for (int q = 0; q < 4; q++) acc[mi][nc][sb][q] = 0.f;

    prop_load_stage(0, 0, b, t, mtile, smem_base, tid);
    asm volatile("cp.async.commit_group;" ::: "memory");

    for (int s = 0; s < 16; s++){
        int buf = s & 1;
        if (s + 1 < 16){
            prop_load_stage(s + 1, buf ^ 1, b, t, mtile, smem_base, tid);
            asm volatile("cp.async.commit_group;" ::: "memory");
            asm volatile("cp.async.wait_group 1;" ::: "memory");
        } else {
            asm volatile("cp.async.wait_group 0;" ::: "memory");
        }
        __syncthreads();

        unsigned ab = smem_base + PROP_HDR + buf*PROP_BUFSZ;
        #pragma unroll
        for (int kk = 0; kk < 4; kk++){
            unsigned aHi[2][4], aLo[2][4];
            #pragma unroll
            for (int mi = 0; mi < 2; mi++){
                unsigned row = m0 + mi*16 + lrow + lq8*8;
                unsigned boff = row*128 + kk*32 + lkhi*16;
                unsigned sw = boff ^ ((boff >> 3) & 0x70);
                ldsm4(aHi[mi][0], aHi[mi][1], aHi[mi][2], aHi[mi][3], ab + sw);
                ldsm4(aLo[mi][0], aLo[mi][1], aLo[mi][2], aLo[mi][3], ab + 16384 + sw);
            }
            #pragma unroll
            for (int nc = 0; nc < 6; nc++){
                unsigned row = n0 + nc*16 + lrow + lq8*8;
                unsigned boff = row*128 + kk*32 + lkhi*16;
                unsigned sw = boff ^ ((boff >> 3) & 0x70);
                unsigned bh[4], bl[4];
                ldsm4(bh[0], bh[1], bh[2], bh[3], ab + 32768 + sw);
                ldsm4(bl[0], bl[1], bl[2], bl[3], ab + 57344 + sw);
                #pragma unroll
                for (int mi = 0; mi < 2; mi++){
                    float* c0 = acc[mi][nc][0];
                    float* c1 = acc[mi][nc][1];
                    mma16816(c0, aHi[mi], bh[0], bh[2]);   // hi*hi
                    mma16816(c1, aHi[mi], bh[1], bh[3]);
                    mma16816(c0, aHi[mi], bl[0], bl[2]);   // hi*lo
                    mma16816(c1, aHi[mi], bl[1], bl[3]);
                    mma16816(c0, aLo[mi], bh[0], bh[2]);   // lo*hi
                    mma16816(c1, aLo[mi], bh[1], bh[3]);
                }
            }
        }
        __syncthreads();   // protect buf before it is overwritten by stage s+2 loads
    }

    // epilogue: write 128x192 fp32 tile
    int g = lane >> 2, cpair = (lane & 3)*2;
    float* Zbase = (dir ? g_Zb : g_Zf);
    #pragma unroll
    for (int mi = 0; mi < 2; mi++){
        int row = (mtile & 7)*128 + m0 + mi*16 + g;
        float* Zp = Zbase + ((size_t)(b*CC + row))*192;
        #pragma unroll
        for (int nc = 0; nc < 6; nc++){
            #pragma unroll
            for (int sb = 0; sb < 2; sb++){
                int col = n0 + nc*16 + sb*8 + cpair;
                float* cc = acc[mi][nc][sb];
                *(float2*)(Zp + col)           = make_float2(cc[0], cc[1]);
                *(float2*)(Zp + 8*192 + col)   = make_float2(cc[2], cc[3]);
            }
        }
    }
}

// ---------------- generic small GEMM: C = act(A@B + bias), M = 8192 ----------------
template<int ACT>
__global__ void __launch_bounds__(256)
gemm_kernel(const float* __restrict__ A, int lda,
            const float* __restrict__ Bm, int ldb,
            const float* __restrict__ bias,
            float* __restrict__ C, int ldc,
            int N, int K)
{
    __shared__ float As[16][132];
    __shared__ float Bs[16][68];
    int m0 = blockIdx.y * 128;
    int n0 = blockIdx.x * 64;
    int tid = threadIdx.x;
    int tx = tid & 15, ty = tid >> 4;
    int arow = tid >> 2, acol = (tid & 3) << 2;
    int brow = tid >> 4, bcol = (tid & 15) << 2;

    float acc[8][4];
    #pragma unroll
    for (int i = 0; i < 8; i++)
        #pragma unroll
        for (int j = 0; j < 4; j++) acc[i][j] = 0.f;

    for (int k0 = 0; k0 < K; k0 += 16){
        float4 a0 = *(const float4*)(A + (size_t)(m0 + arow     )*lda + k0 + acol);
        float4 a1 = *(const float4*)(A + (size_t)(m0 + arow + 64)*lda + k0 + acol);
        As[acol+0][arow] = a0.x; As[acol+1][arow] = a0.y;
        As[acol+2][arow] = a0.z; As[acol+3][arow] = a0.w;
        As[acol+0][arow+64] = a1.x; As[acol+1][arow+64] = a1.y;
        As[acol+2][arow+64] = a1.z; As[acol+3][arow+64] = a1.w;
        float4 bv = make_float4(0.f,0.f,0.f,0.f);
        if (n0 + bcol < N)
            bv = *(const float4*)(Bm + (size_t)(k0 + brow)*ldb + n0 + bcol);
        *(float4*)&Bs[brow][bcol] = bv;
        __syncthreads();
        #pragma unroll
        for (int kk = 0; kk < 16; kk++){
            float4 aA = *(const float4*)&As[kk][ty*8];
            float4 aB = *(const float4*)&As[kk][ty*8 + 4];
            float4 bV = *(const float4*)&Bs[kk][tx*4];
            float av[8] = {aA.x,aA.y,aA.z,aA.w,aB.x,aB.y,aB.z,aB.w};
            float bw[4] = {bV.x,bV.y,bV.z,bV.w};
            #pragma unroll
            for (int i = 0; i < 8; i++)
                #pragma unroll
                for (int j = 0; j < 4; j++) acc[i][j] += av[i]*bw[j];
        }
        __syncthreads();
    }
    int cn = n0 + tx*4;
    if (cn < N){
        float4 bb = *(const float4*)(bias + cn);
        #pragma unroll
        for (int i = 0; i < 8; i++){
            float4 o;
            o.x = acc[i][0] + bb.x;
            o.y = acc[i][1] + bb.y;
            o.z = acc[i][2] + bb.z;
            o.w = acc[i][3] + bb.w;
            if (ACT){
                o.x = fmaxf(o.x, 0.f); o.y = fmaxf(o.y, 0.f);
                o.z = fmaxf(o.z, 0.f); o.w = fmaxf(o.w, 0.f);
            }
            *(float4*)(C + (size_t)(m0 + ty*8 + i)*ldc + cn) = o;
        }
    }
}

// ---------------- GRU gates (h_new = (1-z)*n + z*hs; blends with hs!) ----------------
__global__ void gru_gate_kernel(){
    int idx = blockIdx.x*blockDim.x + threadIdx.x; // ROWS*HH
    int r = idx >> 7, f = idx & 127;
    const float* gi = g_gi + (size_t)r*384;
    const float* gh = g_gh + (size_t)r*384;
    float ir = gi[f], iz = gi[128 + f], inn = gi[256 + f];
    float hr = gh[f], hz = gh[128 + f], hn  = gh[256 + f];
    float rg = 1.f / (1.f + expf(-(ir + hr)));
    float zg = 1.f / (1.f + expf(-(iz + hz)));
    float ng = tanhf(inn + rg*hn);
    float hs = g_xh[(size_t)r*192 + 64 + f];
    g_h[idx] = (1.f - zg)*ng + zg*hs;
}

// ---------------- output scatter ----------------
__global__ void output_kernel(const float* __restrict__ in, float* __restrict__ out, int t){
    int idx = blockIdx.x*blockDim.x + threadIdx.x;
    if (idx >= BB*CC*8) return;
    int q = idx & 7;
    int c = (idx >> 3) & (CC - 1);
    int b = idx >> 13;
    float4 v;
    if (g_mask[c])
        v = *(const float4*)(in + (((size_t)(b*TT + t + 1)*CC + c)*160) + q*4);
    else
        v = *(const float4*)(g_pred + ((size_t)(b*CC + c)*DST) + q*4);
    *(float4*)(out + (((size_t)(b*SS + (t - 4))*CC + c)*DST) + q*4) = v;
}

// ---------------- host orchestration ----------------
static float* symf(const void* s){ void* p = nullptr; cudaGetSymbolAddress(&p, s); return (float*)p; }

extern "C" void kernel_launch(void* const* d_in, const int* in_sizes, int n_in,
                              void* d_out, int out_size)
{
    const float* inputs   = (const float*)d_in[0];
    const float* adj      = (const float*)d_in[1];
    const float* init_W   = (const float*)d_in[2];
    const float* init_b   = (const float*)d_in[3];
    const float* fe_fwd_W = (const float*)d_in[4];
    const float* fe_fwd_b = (const float*)d_in[5];
    const float* fe_bwd_W = (const float*)d_in[6];
    const float* fe_bwd_b = (const float*)d_in[7];
    const float* fwd_W    = (const float*)d_in[8];
    const float* fwd_b    = (const float*)d_in[9];
    const float* bwd_W    = (const float*)d_in[10];
    const float* bwd_b    = (const float*)d_in[11];
    const float* merge_W  = (const float*)d_in[12];
    const float* merge_b  = (const float*)d_in[13];
    const float* gru_Wih  = (const float*)d_in[14];
    const float* gru_bih  = (const float*)d_in[15];
    const float* gru_Whh  = (const float*)d_in[16];
    const float* gru_bhh  = (const float*)d_in[17];
    const float* out_W    = (const float*)d_in[18];
    const float* out_b    = (const float*)d_in[19];
    const int*   cells    = (const int*)  d_in[20];
    float* out = (float*)d_out;

    float* pZf   = symf(g_Zf);
    float* pZb   = symf(g_Zb);
    float* pxh   = symf(g_xh);
    float* pgcat = symf(g_gcat);
    float* pgi   = symf(g_gi);
    float* pgh   = symf(g_gh);
    float* ph    = symf(g_h);
    float* ppred = symf(g_pred);

    cudaFuncSetAttribute(prop_mma_kernel, cudaFuncAttributeMaxDynamicSharedMemorySize, PROP_SMEM);

    // ---- prolog ----
    rowsum_kernel<<<TT*CC/8, 256>>>(adj);
    colsum_kernel<<<dim3(4, TT), 256>>>(adj);
    build_L_kernel<<<dim3(CC/32, CC/32, TT), dim3(32, 8)>>>(adj);
    build_BX_kernel<<<dim3(CC/32, FIN/32, BB*TT), dim3(32, 8)>>>(inputs);
    zero_BH_kernel<<<(BB*HH*CC/2 + 255)/256, 256>>>();
    mask_init_kernel<<<4, 256>>>();
    int nic = in_sizes[20];
    mask_set_kernel<<<(nic + 255)/256, 256>>>(cells, nic);

    // hidden0 = relu(Lf[0] @ x0 @ init_W + init_b)  (BH zeroed; Zf[:, :64] valid)
    prop_mma_kernel<<<dim3(BB, 16), 256, PROP_SMEM>>>(0);
    gemm_kernel<1><<<dim3(2, 64), 256>>>(pZf, 192, init_W, HH, init_b, ph, HH, HH, FIN);
    transpose_h_kernel<<<dim3(CC/32, HH/32, BB), dim3(32, 8)>>>();

    // ---- scan ----
    for (int t = 0; t < TT - 1; t++){
        prop_mma_kernel<<<dim3(BB, 16), 256, PROP_SMEM>>>(t);

        gemm_kernel<1><<<dim3(1, 64), 256>>>(pZf, 192, fe_fwd_W, DST, fe_fwd_b,
                                             pxh + 0, 192, DST, FIN);
        gemm_kernel<1><<<dim3(1, 64), 256>>>(pZb, 192, fe_bwd_W, DST, fe_bwd_b,
                                             pxh + 32, 192, DST, FIN);
        gemm_kernel<1><<<dim3(2, 64), 256>>>(pZf + 64, 192, fwd_W, HH, fwd_b,
                                             pgcat + 0, 256, HH, HH);
        gemm_kernel<1><<<dim3(2, 64), 256>>>(pZb + 64, 192, bwd_W, HH, bwd_b,
                                             pgcat + 128, 256, HH, HH);
        gemm_kernel<0><<<dim3(2, 64), 256>>>(pgcat, 256, merge_W, HH, merge_b,
                                             pxh + 64, 192, HH, 256);
        gemm_kernel<0><<<dim3(6, 64), 256>>>(pxh + 0, 192, gru_Wih, 384, gru_bih,
                                             pgi, 384, 384, FIN);
        gemm_kernel<0><<<dim3(6, 64), 256>>>(pxh + 64, 192, gru_Whh, 384, gru_bhh,
                                             pgh, 384, 384, HH);
        gru_gate_kernel<<<(ROWS*HH)/256, 256>>>();
        transpose_h_kernel<<<dim3(CC/32, HH/32, BB), dim3(32, 8)>>>();

        if (t >= 4){
            gemm_kernel<0><<<dim3(1, 64), 256>>>(ph, HH, out_W, DST, out_b,
                                                 ppred, DST, DST, HH);
            output_kernel<<<(BB*CC*8)/256, 256>>>(inputs, out, t);
        }
    }
}

// round 6
// speedup vs baseline: 1.9637x; 1.2568x over previous
#include <cuda_runtime.h>
#include <cuda_bf16.h>
#include <math.h>

#define BB 8
#define TT 32
#define CC 1024
#define HH 128
#define DST 32
#define FIN 64
#define SS 27            // T - INIT_LENGTH - 1
#define ROWS (BB*CC)     // 8192

// ================= warp-MMA helpers (sm_80-class, compiles on plain sm_103) ==========
__device__ __forceinline__ unsigned smem_u32(const void* p){
    unsigned a;
    asm("{ .reg .u64 t; cvta.to.shared.u64 t, %1; cvt.u32.u64 %0, t; }" : "=r"(a) : "l"(p));
    return a;
}

__device__ __forceinline__ void ldsm4(unsigned& r0, unsigned& r1, unsigned& r2, unsigned& r3,
                                      unsigned addr){
    asm volatile("ldmatrix.sync.aligned.m8n8.x4.shared.b16 {%0,%1,%2,%3}, [%4];"
                 : "=r"(r0), "=r"(r1), "=r"(r2), "=r"(r3) : "r"(addr));
}

__device__ __forceinline__ void mma16816(float* c, const unsigned* a, unsigned b0, unsigned b1){
    asm volatile("mma.sync.aligned.m16n8k16.row.col.f32.bf16.bf16.f32 "
                 "{%0,%1,%2,%3}, {%4,%5,%6,%7}, {%8,%9}, {%0,%1,%2,%3};"
                 : "+f"(c[0]), "+f"(c[1]), "+f"(c[2]), "+f"(c[3])
                 : "r"(a[0]), "r"(a[1]), "r"(a[2]), "r"(a[3]), "r"(b0), "r"(b1));
}

__device__ __forceinline__ void cp16(unsigned dst, const void* src){
    asm volatile("cp.async.cg.shared.global [%0], [%1], 16;"
                 :: "r"(dst), "l"(__cvta_generic_to_global(src)));
}

__device__ __forceinline__ void split_bf16(float v, __nv_bfloat16& hi, __nv_bfloat16& lo){
    hi = __float2bfloat16(v);
    lo = __float2bfloat16(v - __bfloat162float(hi));
}

// ---------------- device scratch (allocation-free contract) ----------------
__device__ __nv_bfloat16 g_LfHi[(size_t)TT*CC*CC];
__device__ __nv_bfloat16 g_LfLo[(size_t)TT*CC*CC];
__device__ __nv_bfloat16 g_LbHi[(size_t)TT*CC*CC];
__device__ __nv_bfloat16 g_LbLo[(size_t)TT*CC*CC];
__device__ __nv_bfloat16 g_BXhi[(size_t)BB*TT*FIN*CC];  // [b][t][f][c]
__device__ __nv_bfloat16 g_BXlo[(size_t)BB*TT*FIN*CC];
__device__ __nv_bfloat16 g_BHhi[(size_t)BB*HH*CC];      // [b][f][c]
__device__ __nv_bfloat16 g_BHlo[(size_t)BB*HH*CC];

__device__ __nv_bfloat16 g_ZfHi[(size_t)ROWS*192], g_ZfLo[(size_t)ROWS*192];
__device__ __nv_bfloat16 g_ZbHi[(size_t)ROWS*192], g_ZbLo[(size_t)ROWS*192];
__device__ __nv_bfloat16 g_tmpHi[(size_t)ROWS*64],  g_tmpLo[(size_t)ROWS*64];
__device__ __nv_bfloat16 g_gcatHi[(size_t)ROWS*256], g_gcatLo[(size_t)ROWS*256];
__device__ __nv_bfloat16 g_hsHi[(size_t)ROWS*128], g_hsLo[(size_t)ROWS*128];

__device__ float g_gi[(size_t)ROWS*384];
__device__ float g_gh[(size_t)ROWS*384];
__device__ float g_h [(size_t)ROWS*HH];
__device__ float g_pred[(size_t)ROWS*DST];
__device__ float g_dinvf[TT*CC];
__device__ float g_dinvb[TT*CC];
__device__ int   g_mask[CC];

// weight splits [N][K]
__device__ __nv_bfloat16 g_WinitHi[128*64],  g_WinitLo[128*64];
__device__ __nv_bfloat16 g_WfeFHi[32*64],    g_WfeFLo[32*64];
__device__ __nv_bfloat16 g_WfeBHi[32*64],    g_WfeBLo[32*64];
__device__ __nv_bfloat16 g_WfwdHi[128*128],  g_WfwdLo[128*128];
__device__ __nv_bfloat16 g_WbwdHi[128*128],  g_WbwdLo[128*128];
__device__ __nv_bfloat16 g_WmergeHi[128*256],g_WmergeLo[128*256];
__device__ __nv_bfloat16 g_WihHi[384*64],    g_WihLo[384*64];
__device__ __nv_bfloat16 g_WhhHi[384*128],   g_WhhLo[384*128];

#define OFF_INIT  0
#define OFF_FEF   128
#define OFF_FEB   160
#define OFF_FWD   192
#define OFF_BWD   320
#define OFF_MERGE 448
#define OFF_BIH   576
#define OFF_BHH   960
__device__ float g_bias[1344];

// ---------------- prolog kernels ----------------
__global__ void rowsum_kernel(const float* __restrict__ adj){
    int warp = (blockIdx.x*blockDim.x + threadIdx.x) >> 5;
    int lane = threadIdx.x & 31;
    if (warp >= TT*CC) return;
    const float* row = adj + (size_t)warp*CC;
    float s = 0.f;
    for (int j = lane; j < CC; j += 32) s += row[j];
    #pragma unroll
    for (int o = 16; o; o >>= 1) s += __shfl_xor_sync(0xffffffffu, s, o);
    if (!lane) g_dinvf[warp] = 1.0f / sqrtf(s + 1.0f);
}

__global__ void colsum_kernel(const float* __restrict__ adj){
    int t = blockIdx.y;
    int i = blockIdx.x*blockDim.x + threadIdx.x;
    const float* base = adj + (size_t)t*CC*CC + i;
    float s = 0.f;
    for (int j = 0; j < CC; j++) s += base[(size_t)j*CC];
    g_dinvb[t*CC + i] = 1.0f / sqrtf(s + 1.0f);
}

__global__ void build_L_kernel(const float* __restrict__ adj){
    __shared__ float tile[32][33];
    int t = blockIdx.z;
    int i0 = blockIdx.y*32, j0 = blockIdx.x*32;
    int tx = threadIdx.x, ty = threadIdx.y; // (32,8)
    const float* df = g_dinvf + t*CC;
    const float* db = g_dinvb + t*CC;
    #pragma unroll
    for (int r = 0; r < 4; r++){
        int li = ty + r*8;
        int i = i0 + li, j = j0 + tx;
        float v = adj[((size_t)t*CC + i)*CC + j] + ((i == j) ? 1.f : 0.f);
        float vf = v * df[i] * df[j];
        __nv_bfloat16 h1, l1;
        split_bf16(vf, h1, l1);
        size_t off = ((size_t)t*CC + i)*CC + j;
        g_LfHi[off] = h1; g_LfLo[off] = l1;
        tile[li][tx] = v * db[i] * db[j];
    }
    __syncthreads();
    #pragma unroll
    for (int r = 0; r < 4; r++){
        int lj = ty + r*8;
        int p = j0 + lj, q = i0 + tx;
        __nv_bfloat16 h1, l1;
        split_bf16(tile[tx][lj], h1, l1);
        size_t off = ((size_t)t*CC + p)*CC + q;
        g_LbHi[off] = h1; g_LbLo[off] = l1;
    }
}

__global__ void build_BX_kernel(const float* __restrict__ in){
    __shared__ float tile[32][33];
    int c0 = blockIdx.x*32, f0 = blockIdx.y*32;
    int bt = blockIdx.z;
    int tx = threadIdx.x, ty = threadIdx.y;
    #pragma unroll
    for (int r = 0; r < 4; r++){
        int c = c0 + ty + r*8;
        int f = f0 + tx;
        int col = (f < 32) ? f : 96 + f;
        tile[ty + r*8][tx] = in[(((size_t)bt*CC) + c)*160 + col];
    }
    __syncthreads();
    #pragma unroll
    for (int r = 0; r < 4; r++){
        int f = f0 + ty + r*8;
        int c = c0 + tx;
        __nv_bfloat16 h1, l1;
        split_bf16(tile[tx][ty + r*8], h1, l1);
        size_t off = (((size_t)bt*FIN) + f)*CC + c;
        g_BXhi[off] = h1; g_BXlo[off] = l1;
    }
}

__global__ void transpose_h_kernel(){
    __shared__ float tile[32][33];
    int c0 = blockIdx.x*32, f0 = blockIdx.y*32;
    int b = blockIdx.z;
    int tx = threadIdx.x, ty = threadIdx.y;
    #pragma unroll
    for (int r = 0; r < 4; r++){
        int c = c0 + ty + r*8;
        int f = f0 + tx;
        tile[ty + r*8][tx] = g_h[((size_t)b*CC + c)*HH + f];
    }
    __syncthreads();
    #pragma unroll
    for (int r = 0; r < 4; r++){
        int f = f0 + ty + r*8;
        int c = c0 + tx;
        __nv_bfloat16 h1, l1;
        split_bf16(tile[tx][ty + r*8], h1, l1);
        size_t off = ((size_t)b*HH + f)*CC + c;
        g_BHhi[off] = h1; g_BHlo[off] = l1;
    }
}

__global__ void zero_BH_kernel(){
    int i = blockIdx.x*blockDim.x + threadIdx.x;
    if (i < BB*HH*CC/2){
        ((unsigned*)g_BHhi)[i] = 0;
        ((unsigned*)g_BHlo)[i] = 0;
    }
}

__global__ void mask_init_kernel(){
    int i = blockIdx.x*blockDim.x + threadIdx.x;
    if (i < CC) g_mask[i] = 0;
}
__global__ void mask_set_kernel(const int* __restrict__ cells, int n){
    int i = blockIdx.x*blockDim.x + threadIdx.x;
    if (i < n) g_mask[cells[i]] = 1;
}

// W fp32 [K][N] -> hi/lo [N][K]
__global__ void wsplit_kernel(const float* __restrict__ W, __nv_bfloat16* hi, __nv_bfloat16* lo,
                              int K, int N){
    int idx = blockIdx.x*blockDim.x + threadIdx.x;
    if (idx >= N*K) return;
    int n = idx / K, k = idx - n*K;
    __nv_bfloat16 h1, l1;
    split_bf16(W[(size_t)k*N + n], h1, l1);
    hi[idx] = h1; lo[idx] = l1;
}

__global__ void bias_copy_kernel(const float* initb, const float* fef, const float* feb,
                                 const float* fwd, const float* bwd, const float* merge,
                                 const float* bih, const float* bhh){
    int i = blockIdx.x*blockDim.x + threadIdx.x;
    if (i < 128){
        g_bias[OFF_INIT + i] = initb[i];
        g_bias[OFF_FWD + i]  = fwd[i];
        g_bias[OFF_BWD + i]  = bwd[i];
        g_bias[OFF_MERGE + i]= merge[i];
    }
    if (i < 32){
        g_bias[OFF_FEF + i] = fef[i];
        g_bias[OFF_FEB + i] = feb[i];
    }
    if (i < 384){
        g_bias[OFF_BIH + i] = bih[i];
        g_bias[OFF_BHH + i] = bhh[i];
    }
}

// ================ HMMA propagation: Z[dir][b] = L[dir][t] @ [x_t | h] ================
#define PROP_HDR   1024
#define PROP_BUFSZ 81920
#define PROP_SMEM  (PROP_HDR + 2*PROP_BUFSZ)

__device__ __forceinline__ void prop_load_stage(int s, int buf, int b, int t, int mtile,
                                                unsigned smem_base, int tid){
    int k0 = s*64;
    unsigned base = smem_base + PROP_HDR + buf*PROP_BUFSZ;
    int dir = mtile >> 3;
    #pragma unroll
    for (int it = 0; it < 20; it++){
        int idx = tid + it*256;
        const __nv_bfloat16* src;
        unsigned sec;
        int row, col, arr;
        if (idx < 2048){
            arr = idx >> 10; int rc = idx & 1023; row = rc >> 3; col = rc & 7;
            const __nv_bfloat16* Lp = dir ? (arr ? g_LbLo : g_LbHi)
                                          : (arr ? g_LfLo : g_LfHi);
            src = Lp + (((size_t)t*CC) + ((mtile & 7)*128 + row))*CC + k0 + col*8;
            sec = arr * 16384u;
        } else {
            int ib = idx - 2048;
            arr = (ib >= 1536); int rc = ib - arr*1536; row = rc >> 3; col = rc & 7;
            if (row < 64){
                const __nv_bfloat16* Xp = arr ? g_BXlo : g_BXhi;
                src = Xp + (((size_t)(b*TT + t)*FIN) + row)*CC + k0 + col*8;
            } else {
                const __nv_bfloat16* Hp = arr ? g_BHlo : g_BHhi;
                src = Hp + (((size_t)b*HH) + (row - 64))*CC + k0 + col*8;
            }
            sec = 32768u + arr*24576u;
        }
        unsigned boff = row*128 + col*16;
        unsigned sw = boff ^ ((boff >> 3) & 0x70);
        cp16(base + sec + sw, src);
    }
}

__device__ __forceinline__ void store_split2(__nv_bfloat16* Hi, __nv_bfloat16* Lo,
                                             size_t off, float v0, float v1){
    __nv_bfloat16 h0, l0, h1, l1;
    split_bf16(v0, h0, l0);
    split_bf16(v1, h1, l1);
    __nv_bfloat162 hh; hh.x = h0; hh.y = h1;
    __nv_bfloat162 ll; ll.x = l0; ll.y = l1;
    *(__nv_bfloat162*)(Hi + off) = hh;
    *(__nv_bfloat162*)(Lo + off) = ll;
}

__global__ void __launch_bounds__(256) prop_mma_kernel(int t){
    extern __shared__ char smem[];
    unsigned smem_base = smem_u32(smem);
    int tid = threadIdx.x;
    int b = blockIdx.x;
    int mtile = blockIdx.y;
    int dir = mtile >> 3;

    int wid = tid >> 5;
    int lane = tid & 31;
    int m0 = (wid >> 1) * 32;
    int n0 = (wid & 1) * 96;
    int lrow = lane & 7;
    int lq8  = (lane >> 3) & 1;
    int lkhi = lane >> 4;

    float acc[2][6][2][4];
    #pragma unroll
    for (int mi = 0; mi < 2; mi++)
        #pragma unroll
        for (int nc = 0; nc < 6; nc++)
            #pragma unroll
            for (int sb = 0; sb < 2; sb++)
                #pragma unroll
                for (int q = 0; q < 4; q++) acc[mi][nc][sb][q] = 0.f;

    prop_load_stage(0, 0, b, t, mtile, smem_base, tid);
    asm volatile("cp.async.commit_group;" ::: "memory");

    for (int s = 0; s < 16; s++){
        int buf = s & 1;
        if (s + 1 < 16){
            prop_load_stage(s + 1, buf ^ 1, b, t, mtile, smem_base, tid);
            asm volatile("cp.async.commit_group;" ::: "memory");
            asm volatile("cp.async.wait_group 1;" ::: "memory");
        } else {
            asm volatile("cp.async.wait_group 0;" ::: "memory");
        }
        __syncthreads();

        unsigned ab = smem_base + PROP_HDR + buf*PROP_BUFSZ;
        #pragma unroll
        for (int kk = 0; kk < 4; kk++){
            unsigned aHi[2][4], aLo[2][4];
            #pragma unroll
            for (int mi = 0; mi < 2; mi++){
                unsigned row = m0 + mi*16 + lrow + lq8*8;
                unsigned boff = row*128 + kk*32 + lkhi*16;
                unsigned sw = boff ^ ((boff >> 3) & 0x70);
                ldsm4(aHi[mi][0], aHi[mi][1], aHi[mi][2], aHi[mi][3], ab + sw);
                ldsm4(aLo[mi][0], aLo[mi][1], aLo[mi][2], aLo[mi][3], ab + 16384 + sw);
            }
            #pragma unroll
            for (int nc = 0; nc < 6; nc++){
                unsigned row = n0 + nc*16 + lrow + lq8*8;
                unsigned boff = row*128 + kk*32 + lkhi*16;
                unsigned sw = boff ^ ((boff >> 3) & 0x70);
                unsigned bh[4], bl[4];
                ldsm4(bh[0], bh[1], bh[2], bh[3], ab + 32768 + sw);
                ldsm4(bl[0], bl[1], bl[2], bl[3], ab + 57344 + sw);
                #pragma unroll
                for (int mi = 0; mi < 2; mi++){
                    float* c0 = acc[mi][nc][0];
                    float* c1 = acc[mi][nc][1];
                    mma16816(c0, aHi[mi], bh[0], bh[2]);
                    mma16816(c1, aHi[mi], bh[1], bh[3]);
                    mma16816(c0, aHi[mi], bl[0], bl[2]);
                    mma16816(c1, aHi[mi], bl[1], bl[3]);
                    mma16816(c0, aLo[mi], bh[0], bh[2]);
                    mma16816(c1, aLo[mi], bh[1], bh[3]);
                }
            }
        }
        __syncthreads();
    }

    // epilogue: write 128x192 tile as split bf16
    int g = lane >> 2, cpair = (lane & 3)*2;
    __nv_bfloat16* Zh = dir ? g_ZbHi : g_ZfHi;
    __nv_bfloat16* Zl = dir ? g_ZbLo : g_ZfLo;
    #pragma unroll
    for (int mi = 0; mi < 2; mi++){
        int row = (mtile & 7)*128 + m0 + mi*16 + g;
        size_t rbase = ((size_t)(b*CC + row))*192;
        #pragma unroll
        for (int nc = 0; nc < 6; nc++){
            #pragma unroll
            for (int sb = 0; sb < 2; sb++){
                int col = n0 + nc*16 + sb*8 + cpair;
                float* cc = acc[mi][nc][sb];
                store_split2(Zh, Zl, rbase + col,          cc[0], cc[1]);
                store_split2(Zh, Zl, rbase + 8*192 + col,  cc[2], cc[3]);
            }
        }
    }
}

// ================ generic HMMA small GEMM (task table) ================
__device__ __forceinline__ void sg_load_stage(unsigned base,
    const __nv_bfloat16* Ahi, const __nv_bfloat16* Alo, int lda,
    const __nv_bfloat16* Whi, const __nv_bfloat16* Wlo, int K, int N,
    int k0, int mtile, int tid)
{
    int total = 2048 + N*16;
    for (int idx = tid; idx < total; idx += 256){
        const __nv_bfloat16* src;
        unsigned sec;
        int row, col;
        if (idx < 2048){
            int arr = idx >> 10; int rc = idx & 1023; row = rc >> 3; col = rc & 7;
            src = (arr ? Alo : Ahi) + (size_t)(mtile*128 + row)*lda + k0 + col*8;
            sec = arr * 16384u;
        } else {
            int ib = idx - 2048; int half = N*8;
            int arr = (ib >= half); int rc = ib - arr*half; row = rc >> 3; col = rc & 7;
            src = (arr ? Wlo : Whi) + (size_t)row*K + k0 + col*8;
            sec = 32768u + arr*24576u;
        }
        unsigned boff = row*128 + col*16;
        unsigned sw = boff ^ ((boff >> 3) & 0x70);
        cp16(base + sec + sw, src);
    }
}

__global__ void __launch_bounds__(256) sgemm_kernel(int basecfg){
    int which = basecfg + blockIdx.y;
    const __nv_bfloat16 *Ahi, *Alo, *Whi, *Wlo;
    int lda, K, N, ldc, act = 0;
    const float* bias;
    float* Cf = nullptr;
    __nv_bfloat16 *Chi = nullptr, *Clo = nullptr;

    switch (which){
    case 0: Ahi=g_ZfHi; Alo=g_ZfLo; lda=192; K=64; Whi=g_WfeFHi; Wlo=g_WfeFLo; N=32;
            bias=g_bias+OFF_FEF; Chi=g_tmpHi; Clo=g_tmpLo; ldc=64; act=1; break;
    case 1: Ahi=g_ZbHi; Alo=g_ZbLo; lda=192; K=64; Whi=g_WfeBHi; Wlo=g_WfeBLo; N=32;
            bias=g_bias+OFF_FEB; Chi=g_tmpHi+32; Clo=g_tmpLo+32; ldc=64; act=1; break;
    case 2: Ahi=g_ZfHi+64; Alo=g_ZfLo+64; lda=192; K=128; Whi=g_WfwdHi; Wlo=g_WfwdLo; N=128;
            bias=g_bias+OFF_FWD; Chi=g_gcatHi; Clo=g_gcatLo; ldc=256; act=1; break;
    case 3: Ahi=g_ZbHi+64; Alo=g_ZbLo+64; lda=192; K=128; Whi=g_WbwdHi; Wlo=g_WbwdLo; N=128;
            bias=g_bias+OFF_BWD; Chi=g_gcatHi+128; Clo=g_gcatLo+128; ldc=256; act=1; break;
    case 4: Ahi=g_gcatHi; Alo=g_gcatLo; lda=256; K=256; Whi=g_WmergeHi; Wlo=g_WmergeLo; N=128;
            bias=g_bias+OFF_MERGE; Chi=g_hsHi; Clo=g_hsLo; ldc=128; break;
    case 5: case 6: {
        int j = which - 5;
        Ahi=g_tmpHi; Alo=g_tmpLo; lda=64; K=64; Whi=g_WihHi + j*192*64; Wlo=g_WihLo + j*192*64;
        N=192; bias=g_bias+OFF_BIH+j*192; Cf=g_gi + j*192; ldc=384; break; }
    case 7: case 8: {
        int j = which - 7;
        Ahi=g_hsHi; Alo=g_hsLo; lda=128; K=128; Whi=g_WhhHi + j*192*128; Wlo=g_WhhLo + j*192*128;
        N=192; bias=g_bias+OFF_BHH+j*192; Cf=g_gh + j*192; ldc=384; break; }
    default: // 9: init
        Ahi=g_ZfHi; Alo=g_ZfLo; lda=192; K=64; Whi=g_WinitHi; Wlo=g_WinitLo; N=128;
        bias=g_bias+OFF_INIT; Cf=g_h; ldc=128; act=1; break;
    }

    extern __shared__ char smem[];
    unsigned smem_base = smem_u32(smem);
    int tid = threadIdx.x;
    int mtile = blockIdx.x;
    int wid = tid >> 5;
    int lane = tid & 31;
    int m0 = (wid >> 1) * 32;
    int Nw = N >> 1;
    int n0 = (wid & 1) * Nw;
    int ncCount = Nw >> 4;
    int lrow = lane & 7;
    int lq8  = (lane >> 3) & 1;
    int lkhi = lane >> 4;
    int nstages = K >> 6;

    float acc[2][6][2][4];
    #pragma unroll
    for (int mi = 0; mi < 2; mi++)
        #pragma unroll
        for (int nc = 0; nc < 6; nc++)
            #pragma unroll
            for (int sb = 0; sb < 2; sb++)
                #pragma unroll
                for (int q = 0; q < 4; q++) acc[mi][nc][sb][q] = 0.f;

    sg_load_stage(smem_base + PROP_HDR, Ahi, Alo, lda, Whi, Wlo, K, N, 0, mtile, tid);
    asm volatile("cp.async.commit_group;" ::: "memory");

    for (int s = 0; s < nstages; s++){
        int buf = s & 1;
        if (s + 1 < nstages){
            sg_load_stage(smem_base + PROP_HDR + (buf^1)*PROP_BUFSZ,
                          Ahi, Alo, lda, Whi, Wlo, K, N, (s+1)*64, mtile, tid);
            asm volatile("cp.async.commit_group;" ::: "memory");
            asm volatile("cp.async.wait_group 1;" ::: "memory");
        } else {
            asm volatile("cp.async.wait_group 0;" ::: "memory");
        }
        __syncthreads();

        unsigned ab = smem_base + PROP_HDR + buf*PROP_BUFSZ;
        #pragma unroll
        for (int kk = 0; kk < 4; kk++){
            unsigned aHi[2][4], aLo[2][4];
            #pragma unroll
            for (int mi = 0; mi < 2; mi++){
                unsigned row = m0 + mi*16 + lrow + lq8*8;
                unsigned boff = row*128 + kk*32 + lkhi*16;
                unsigned sw = boff ^ ((boff >> 3) & 0x70);
                ldsm4(aHi[mi][0], aHi[mi][1], aHi[mi][2], aHi[mi][3], ab + sw);
                ldsm4(aLo[mi][0], aLo[mi][1], aLo[mi][2], aLo[mi][3], ab + 16384 + sw);
            }
            for (int nc = 0; nc < ncCount; nc++){
                unsigned row = n0 + nc*16 + lrow + lq8*8;
                unsigned boff = row*128 + kk*32 + lkhi*16;
                unsigned sw = boff ^ ((boff >> 3) & 0x70);
                unsigned bh[4], bl[4];
                ldsm4(bh[0], bh[1], bh[2], bh[3], ab + 32768 + sw);
                ldsm4(bl[0], bl[1], bl[2], bl[3], ab + 57344 + sw);
                #pragma unroll
                for (int mi = 0; mi < 2; mi++){
                    float* c0 = acc[mi][nc][0];
                    float* c1 = acc[mi][nc][1];
                    mma16816(c0, aHi[mi], bh[0], bh[2]);
                    mma16816(c1, aHi[mi], bh[1], bh[3]);
                    mma16816(c0, aHi[mi], bl[0], bl[2]);
                    mma16816(c1, aHi[mi], bl[1], bl[3]);
                    mma16816(c0, aLo[mi], bh[0], bh[2]);
                    mma16816(c1, aLo[mi], bh[1], bh[3]);
                }
            }
        }
        __syncthreads();
    }

    int g = lane >> 2, cpair = (lane & 3)*2;
    #pragma unroll
    for (int mi = 0; mi < 2; mi++){
        int row = mtile*128 + m0 + mi*16 + g;
        for (int nc = 0; nc < ncCount; nc++){
            #pragma unroll
            for (int sb = 0; sb < 2; sb++){
                int col = n0 + nc*16 + sb*8 + cpair;
                float b0 = bias[col], b1 = bias[col+1];
                float* cc = acc[mi][nc][sb];
                float v00 = cc[0] + b0, v01 = cc[1] + b1;
                float v10 = cc[2] + b0, v11 = cc[3] + b1;
                if (act){
                    v00 = fmaxf(v00, 0.f); v01 = fmaxf(v01, 0.f);
                    v10 = fmaxf(v10, 0.f); v11 = fmaxf(v11, 0.f);
                }
                if (Cf){
                    *(float2*)(Cf + (size_t)row*ldc + col)       = make_float2(v00, v01);
                    *(float2*)(Cf + (size_t)(row+8)*ldc + col)   = make_float2(v10, v11);
                } else {
                    store_split2(Chi, Clo, (size_t)row*ldc + col,     v00, v01);
                    store_split2(Chi, Clo, (size_t)(row+8)*ldc + col, v10, v11);
                }
            }
        }
    }
}

// ---------------- fp32 small GEMM (kept for out projection) ----------------
__global__ void __launch_bounds__(256)
gemm_f32_kernel(const float* __restrict__ A, int lda,
                const float* __restrict__ Bm, int ldb,
                const float* __restrict__ bias,
                float* __restrict__ C, int ldc,
                int N, int K)
{
    __shared__ float As[16][132];
    __shared__ float Bs[16][68];
    int m0 = blockIdx.y * 128;
    int n0 = blockIdx.x * 64;
    int tid = threadIdx.x;
    int tx = tid & 15, ty = tid >> 4;
    int arow = tid >> 2, acol = (tid & 3) << 2;
    int brow = tid >> 4, bcol = (tid & 15) << 2;

    float acc[8][4];
    #pragma unroll
    for (int i = 0; i < 8; i++)
        #pragma unroll
        for (int j = 0; j < 4; j++) acc[i][j] = 0.f;

    for (int k0 = 0; k0 < K; k0 += 16){
        float4 a0 = *(const float4*)(A + (size_t)(m0 + arow     )*lda + k0 + acol);
        float4 a1 = *(const float4*)(A + (size_t)(m0 + arow + 64)*lda + k0 + acol);
        As[acol+0][arow] = a0.x; As[acol+1][arow] = a0.y;
        As[acol+2][arow] = a0.z; As[acol+3][arow] = a0.w;
        As[acol+0][arow+64] = a1.x; As[acol+1][arow+64] = a1.y;
        As[acol+2][arow+64] = a1.z; As[acol+3][arow+64] = a1.w;
        float4 bv = make_float4(0.f,0.f,0.f,0.f);
        if (n0 + bcol < N)
            bv = *(const float4*)(Bm + (size_t)(k0 + brow)*ldb + n0 + bcol);
        *(float4*)&Bs[brow][bcol] = bv;
        __syncthreads();
        #pragma unroll
        for (int kk = 0; kk < 16; kk++){
            float4 aA = *(const float4*)&As[kk][ty*8];
            float4 aB = *(const float4*)&As[kk][ty*8 + 4];
            float4 bV = *(const float4*)&Bs[kk][tx*4];
            float av[8] = {aA.x,aA.y,aA.z,aA.w,aB.x,aB.y,aB.z,aB.w};
            float bw[4] = {bV.x,bV.y,bV.z,bV.w};
            #pragma unroll
            for (int i = 0; i < 8; i++)
                #pragma unroll
                for (int j = 0; j < 4; j++) acc[i][j] += av[i]*bw[j];
        }
        __syncthreads();
    }
    int cn = n0 + tx*4;
    if (cn < N){
        float4 bb = *(const float4*)(bias + cn);
        #pragma unroll
        for (int i = 0; i < 8; i++){
            float4 o;
            o.x = acc[i][0] + bb.x;
            o.y = acc[i][1] + bb.y;
            o.z = acc[i][2] + bb.z;
            o.w = acc[i][3] + bb.w;
            *(float4*)(C + (size_t)(m0 + ty*8 + i)*ldc + cn) = o;
        }
    }
}

// ---------------- GRU gates (h_new = (1-z)*n + z*hs; blends with hs!) ----------------
__global__ void gru_gate_kernel(){
    int idx = blockIdx.x*blockDim.x + threadIdx.x; // ROWS*HH
    int r = idx >> 7, f = idx & 127;
    const float* gi = g_gi + (size_t)r*384;
    const float* gh = g_gh + (size_t)r*384;
    float ir = gi[f], iz = gi[128 + f], inn = gi[256 + f];
    float hr = gh[f], hz = gh[128 + f], hn  = gh[256 + f];
    float rg = 1.f / (1.f + expf(-(ir + hr)));
    float zg = 1.f / (1.f + expf(-(iz + hz)));
    float ng = tanhf(inn + rg*hn);
    size_t ho = (size_t)r*128 + f;
    float hs = __bfloat162float(g_hsHi[ho]) + __bfloat162float(g_hsLo[ho]);
    g_h[idx] = (1.f - zg)*ng + zg*hs;
}

// ---------------- output scatter ----------------
__global__ void output_kernel(const float* __restrict__ in, float* __restrict__ out, int t){
    int idx = blockIdx.x*blockDim.x + threadIdx.x;
    if (idx >= BB*CC*8) return;
    int q = idx & 7;
    int c = (idx >> 3) & (CC - 1);
    int b = idx >> 13;
    float4 v;
    if (g_mask[c])
        v = *(const float4*)(in + (((size_t)(b*TT + t + 1)*CC + c)*160) + q*4);
    else
        v = *(const float4*)(g_pred + ((size_t)(b*CC + c)*DST) + q*4);
    *(float4*)(out + (((size_t)(b*SS + (t - 4))*CC + c)*DST) + q*4) = v;
}

// ---------------- host orchestration ----------------
static float* symf(const void* s){ void* p = nullptr; cudaGetSymbolAddress(&p, s); return (float*)p; }
static __nv_bfloat16* symb(const void* s){ void* p = nullptr; cudaGetSymbolAddress(&p, s); return (__nv_bfloat16*)p; }

extern "C" void kernel_launch(void* const* d_in, const int* in_sizes, int n_in,
                              void* d_out, int out_size)
{
    const float* inputs   = (const float*)d_in[0];
    const float* adj      = (const float*)d_in[1];
    const float* init_W   = (const float*)d_in[2];
    const float* init_b   = (const float*)d_in[3];
    const float* fe_fwd_W = (const float*)d_in[4];
    const float* fe_fwd_b = (const float*)d_in[5];
    const float* fe_bwd_W = (const float*)d_in[6];
    const float* fe_bwd_b = (const float*)d_in[7];
    const float* fwd_W    = (const float*)d_in[8];
    const float* fwd_b    = (const float*)d_in[9];
    const float* bwd_W    = (const float*)d_in[10];
    const float* bwd_b    = (const float*)d_in[11];
    const float* merge_W  = (const float*)d_in[12];
    const float* merge_b  = (const float*)d_in[13];
    const float* gru_Wih  = (const float*)d_in[14];
    const float* gru_bih  = (const float*)d_in[15];
    const float* gru_Whh  = (const float*)d_in[16];
    const float* gru_bhh  = (const float*)d_in[17];
    const float* out_W    = (const float*)d_in[18];
    const float* out_b    = (const float*)d_in[19];
    const int*   cells    = (const int*)  d_in[20];
    float* out = (float*)d_out;

    float* ph    = symf(g_h);
    float* ppred = symf(g_pred);

    cudaFuncSetAttribute(prop_mma_kernel, cudaFuncAttributeMaxDynamicSharedMemorySize, PROP_SMEM);
    cudaFuncSetAttribute(sgemm_kernel,    cudaFuncAttributeMaxDynamicSharedMemorySize, PROP_SMEM);

    // ---- prolog ----
    rowsum_kernel<<<TT*CC/8, 256>>>(adj);
    colsum_kernel<<<dim3(4, TT), 256>>>(adj);
    build_L_kernel<<<dim3(CC/32, CC/32, TT), dim3(32, 8)>>>(adj);
    build_BX_kernel<<<dim3(CC/32, FIN/32, BB*TT), dim3(32, 8)>>>(inputs);
    zero_BH_kernel<<<(BB*HH*CC/2 + 255)/256, 256>>>();
    mask_init_kernel<<<4, 256>>>();
    int nic = in_sizes[20];
    mask_set_kernel<<<(nic + 255)/256, 256>>>(cells, nic);

    wsplit_kernel<<<(128*64 + 255)/256, 256>>>(init_W,  symb(g_WinitHi), symb(g_WinitLo), 64, 128);
    wsplit_kernel<<<(32*64 + 255)/256, 256>>>(fe_fwd_W, symb(g_WfeFHi),  symb(g_WfeFLo),  64, 32);
    wsplit_kernel<<<(32*64 + 255)/256, 256>>>(fe_bwd_W, symb(g_WfeBHi),  symb(g_WfeBLo),  64, 32);
    wsplit_kernel<<<(128*128 + 255)/256, 256>>>(fwd_W,  symb(g_WfwdHi),  symb(g_WfwdLo),  128, 128);
    wsplit_kernel<<<(128*128 + 255)/256, 256>>>(bwd_W,  symb(g_WbwdHi),  symb(g_WbwdLo),  128, 128);
    wsplit_kernel<<<(128*256 + 255)/256, 256>>>(merge_W,symb(g_WmergeHi),symb(g_WmergeLo),256, 128);
    wsplit_kernel<<<(384*64 + 255)/256, 256>>>(gru_Wih, symb(g_WihHi),   symb(g_WihLo),   64, 384);
    wsplit_kernel<<<(384*128 + 255)/256, 256>>>(gru_Whh,symb(g_WhhHi),   symb(g_WhhLo),   128, 384);
    bias_copy_kernel<<<2, 256>>>(init_b, fe_fwd_b, fe_bwd_b, fwd_b, bwd_b, merge_b,
                                 gru_bih, gru_bhh);

    // hidden0 = relu(Lf[0] @ x0 @ init_W + init_b)
    prop_mma_kernel<<<dim3(BB, 16), 256, PROP_SMEM>>>(0);
    sgemm_kernel<<<dim3(64, 1), 256, PROP_SMEM>>>(9);
    transpose_h_kernel<<<dim3(CC/32, HH/32, BB), dim3(32, 8)>>>();

    // ---- scan ----
    for (int t = 0; t < TT - 1; t++){
        prop_mma_kernel<<<dim3(BB, 16), 256, PROP_SMEM>>>(t);
        sgemm_kernel<<<dim3(64, 4), 256, PROP_SMEM>>>(0);  // fe_fwd, fe_bwd, fwd, bwd
        sgemm_kernel<<<dim3(64, 1), 256, PROP_SMEM>>>(4);  // merge -> hs
        sgemm_kernel<<<dim3(64, 4), 256, PROP_SMEM>>>(5);  // gi (2 tiles), gh (2 tiles)
        gru_gate_kernel<<<(ROWS*HH)/256, 256>>>();
        transpose_h_kernel<<<dim3(CC/32, HH/32, BB), dim3(32, 8)>>>();

        if (t >= 4){
            gemm_f32_kernel<<<dim3(1, 64), 256>>>(ph, HH, out_W, DST, out_b,
                                                  ppred, DST, DST, HH);
            output_kernel<<<(BB*CC*8)/256, 256>>>(inputs, out, t);
        }
    }
}

// round 7
// speedup vs baseline: 4.0321x; 2.0533x over previous
#include <cuda_runtime.h>
#include <cuda_bf16.h>
#include <math.h>

#define BB 8
#define TT 32
#define CC 1024
#define HH 128
#define DST 32
#define FIN 64
#define SS 27            // T - INIT_LENGTH - 1
#define NT 31            // scan steps
#define ROWS (BB*CC)     // 8192

// ================= warp-MMA helpers =================
__device__ __forceinline__ unsigned smem_u32(const void* p){
    unsigned a;
    asm("{ .reg .u64 t; cvta.to.shared.u64 t, %1; cvt.u32.u64 %0, t; }" : "=r"(a) : "l"(p));
    return a;
}

__device__ __forceinline__ void ldsm4(unsigned& r0, unsigned& r1, unsigned& r2, unsigned& r3,
                                      unsigned addr){
    asm volatile("ldmatrix.sync.aligned.m8n8.x4.shared.b16 {%0,%1,%2,%3}, [%4];"
                 : "=r"(r0), "=r"(r1), "=r"(r2), "=r"(r3) : "r"(addr));
}

__device__ __forceinline__ void mma16816(float* c, const unsigned* a, unsigned b0, unsigned b1){
    asm volatile("mma.sync.aligned.m16n8k16.row.col.f32.bf16.bf16.f32 "
                 "{%0,%1,%2,%3}, {%4,%5,%6,%7}, {%8,%9}, {%0,%1,%2,%3};"
                 : "+f"(c[0]), "+f"(c[1]), "+f"(c[2]), "+f"(c[3])
                 : "r"(a[0]), "r"(a[1]), "r"(a[2]), "r"(a[3]), "r"(b0), "r"(b1));
}

__device__ __forceinline__ void cp16(unsigned dst, const void* src){
    asm volatile("cp.async.cg.shared.global [%0], [%1], 16;"
                 :: "r"(dst), "l"(__cvta_generic_to_global(src)));
}

// ---------------- device scratch ----------------
__device__ __nv_bfloat16 g_Lf[(size_t)TT*CC*CC];       // 64 MB
__device__ __nv_bfloat16 g_Lb[(size_t)TT*CC*CC];       // 64 MB (transposed)
__device__ __nv_bfloat16 g_BX[(size_t)BB*TT*FIN*CC];   // [b][t][f][c]
__device__ __nv_bfloat16 g_BH[(size_t)BB*HH*CC];       // [b][f][c]

__device__ __nv_bfloat16 g_Zxf[(size_t)NT*ROWS*64];    // [t][row][64]
__device__ __nv_bfloat16 g_Zxb[(size_t)NT*ROWS*64];
__device__ __nv_bfloat16 g_Zhf[(size_t)ROWS*HH];
__device__ __nv_bfloat16 g_Zhb[(size_t)ROWS*HH];
__device__ __nv_bfloat16 g_tmp[(size_t)NT*ROWS*64];    // fe outputs [t][row][64]
__device__ float         g_gi_all[(size_t)NT*ROWS*384];// 390 MB
__device__ __nv_bfloat16 g_gcat[(size_t)ROWS*256];
__device__ float         g_hsf[(size_t)ROWS*HH];
__device__ __nv_bfloat16 g_hsb[(size_t)ROWS*HH];
__device__ float         g_gh[(size_t)ROWS*384];
__device__ float         g_hist[(size_t)SS*ROWS*HH];   // h for t=4..30
__device__ float         g_h[(size_t)ROWS*HH];
__device__ float         g_dinvf[TT*CC];
__device__ float         g_dinvb[TT*CC];
__device__ int           g_mask[CC];

// weights bf16 [N][K]
__device__ __nv_bfloat16 g_Winit[128*64];
__device__ __nv_bfloat16 g_WfeF[32*64];
__device__ __nv_bfloat16 g_WfeB[32*64];
__device__ __nv_bfloat16 g_Wfwd[128*128];
__device__ __nv_bfloat16 g_Wbwd[128*128];
__device__ __nv_bfloat16 g_Wmerge[128*256];
__device__ __nv_bfloat16 g_Wih[384*64];
__device__ __nv_bfloat16 g_Whh[384*128];

#define OFF_INIT  0
#define OFF_FEF   128
#define OFF_FEB   160
#define OFF_FWD   192
#define OFF_BWD   320
#define OFF_MERGE 448
#define OFF_BIH   576
#define OFF_BHH   960
__device__ float g_bias[1344];

// ---------------- prolog kernels ----------------
__global__ void rowsum_kernel(const float* __restrict__ adj){
    int warp = (blockIdx.x*blockDim.x + threadIdx.x) >> 5;
    int lane = threadIdx.x & 31;
    if (warp >= TT*CC) return;
    const float* row = adj + (size_t)warp*CC;
    float s = 0.f;
    for (int j = lane; j < CC; j += 32) s += row[j];
    #pragma unroll
    for (int o = 16; o; o >>= 1) s += __shfl_xor_sync(0xffffffffu, s, o);
    if (!lane) g_dinvf[warp] = 1.0f / sqrtf(s + 1.0f);
}

__global__ void colsum_kernel(const float* __restrict__ adj){
    int t = blockIdx.y;
    int i = blockIdx.x*blockDim.x + threadIdx.x;
    const float* base = adj + (size_t)t*CC*CC + i;
    float s = 0.f;
    for (int j = 0; j < CC; j++) s += base[(size_t)j*CC];
    g_dinvb[t*CC + i] = 1.0f / sqrtf(s + 1.0f);
}

__global__ void build_L_kernel(const float* __restrict__ adj){
    __shared__ float tile[32][33];
    int t = blockIdx.z;
    int i0 = blockIdx.y*32, j0 = blockIdx.x*32;
    int tx = threadIdx.x, ty = threadIdx.y; // (32,8)
    const float* df = g_dinvf + t*CC;
    const float* db = g_dinvb + t*CC;
    #pragma unroll
    for (int r = 0; r < 4; r++){
        int li = ty + r*8;
        int i = i0 + li, j = j0 + tx;
        float v = adj[((size_t)t*CC + i)*CC + j] + ((i == j) ? 1.f : 0.f);
        g_Lf[((size_t)t*CC + i)*CC + j] = __float2bfloat16(v * df[i] * df[j]);
        tile[li][tx] = v * db[i] * db[j];
    }
    __syncthreads();
    #pragma unroll
    for (int r = 0; r < 4; r++){
        int lj = ty + r*8;
        int p = j0 + lj, q = i0 + tx;
        g_Lb[((size_t)t*CC + p)*CC + q] = __float2bfloat16(tile[tx][lj]);
    }
}

__global__ void build_BX_kernel(const float* __restrict__ in){
    __shared__ float tile[32][33];
    int c0 = blockIdx.x*32, f0 = blockIdx.y*32;
    int bt = blockIdx.z;
    int tx = threadIdx.x, ty = threadIdx.y;
    #pragma unroll
    for (int r = 0; r < 4; r++){
        int c = c0 + ty + r*8;
        int f = f0 + tx;
        int col = (f < 32) ? f : 96 + f;
        tile[ty + r*8][tx] = in[(((size_t)bt*CC) + c)*160 + col];
    }
    __syncthreads();
    #pragma unroll
    for (int r = 0; r < 4; r++){
        int f = f0 + ty + r*8;
        int c = c0 + tx;
        g_BX[(((size_t)bt*FIN) + f)*CC + c] = __float2bfloat16(tile[tx][ty + r*8]);
    }
}

// h fp32 [row][128] -> BH bf16 [b][f][c]  (used once for hidden0)
__global__ void transpose_h_kernel(){
    __shared__ float tile[32][33];
    int c0 = blockIdx.x*32, f0 = blockIdx.y*32;
    int b = blockIdx.z;
    int tx = threadIdx.x, ty = threadIdx.y;
    #pragma unroll
    for (int r = 0; r < 4; r++){
        int c = c0 + ty + r*8;
        int f = f0 + tx;
        tile[ty + r*8][tx] = g_h[((size_t)b*CC + c)*HH + f];
    }
    __syncthreads();
    #pragma unroll
    for (int r = 0; r < 4; r++){
        int f = f0 + ty + r*8;
        int c = c0 + tx;
        g_BH[((size_t)b*HH + f)*CC + c] = __float2bfloat16(tile[tx][ty + r*8]);
    }
}

__global__ void mask_init_kernel(){
    int i = blockIdx.x*blockDim.x + threadIdx.x;
    if (i < CC) g_mask[i] = 0;
}
__global__ void mask_set_kernel(const int* __restrict__ cells, int n){
    int i = blockIdx.x*blockDim.x + threadIdx.x;
    if (i < n) g_mask[cells[i]] = 1;
}

// W fp32 [K][N] -> bf16 [N][K]
__global__ void wconv_kernel(const float* __restrict__ W, __nv_bfloat16* w, int K, int N){
    int idx = blockIdx.x*blockDim.x + threadIdx.x;
    if (idx >= N*K) return;
    int n = idx / K, k = idx - n*K;
    w[idx] = __float2bfloat16(W[(size_t)k*N + n]);
}

__global__ void bias_copy_kernel(const float* initb, const float* fef, const float* feb,
                                 const float* fwd, const float* bwd, const float* merge,
                                 const float* bih, const float* bhh){
    int i = blockIdx.x*blockDim.x + threadIdx.x;
    if (i < 128){
        g_bias[OFF_INIT + i] = initb[i];
        g_bias[OFF_FWD + i]  = fwd[i];
        g_bias[OFF_BWD + i]  = bwd[i];
        g_bias[OFF_MERGE + i]= merge[i];
    }
    if (i < 32){
        g_bias[OFF_FEF + i] = fef[i];
        g_bias[OFF_FEB + i] = feb[i];
    }
    if (i < 384){
        g_bias[OFF_BIH + i] = bih[i];
        g_bias[OFF_BHH + i] = bhh[i];
    }
}

// ================ propagation: Z = L @ B  (single-pass bf16 HMMA) ================
// MODE 0: x-prop, grid (b=8, mtile=8, z=t*2+dir), NB=64, dst Zx[t]
// MODE 1: h-prop, grid (b=8, y=dir*8+mtile),      NB=128, dst Zh
template<int NB, int MODE>
__global__ void __launch_bounds__(256) prop_kernel(int t_param){
    constexpr int NCC = NB/32;
    constexpr int BUFSZ = 16384 + NB*128;
    constexpr int TOTAL = 1024 + NB*8;
    extern __shared__ char smem[];
    unsigned smem_base = smem_u32(smem);
    int tid = threadIdx.x;
    int b = blockIdx.x;
    int mtile, dir, t;
    if (MODE == 0){ mtile = blockIdx.y; t = blockIdx.z >> 1; dir = blockIdx.z & 1; }
    else          { mtile = blockIdx.y & 7; dir = blockIdx.y >> 3; t = t_param; }

    const __nv_bfloat16* L = (dir ? g_Lb : g_Lf) + (size_t)t*CC*CC + (size_t)mtile*128*CC;
    const __nv_bfloat16* Bsrc;
    __nv_bfloat16* Zdst;
    int ldz;
    if (MODE == 0){
        Bsrc = g_BX + (size_t)(b*TT + t)*FIN*CC;
        Zdst = (dir ? g_Zxb : g_Zxf) + ((size_t)t*ROWS + b*CC + mtile*128)*64;
        ldz = 64;
    } else {
        Bsrc = g_BH + (size_t)b*HH*CC;
        Zdst = (dir ? g_Zhb : g_Zhf) + ((size_t)(b*CC + mtile*128))*HH;
        ldz = HH;
    }

    int wid = tid >> 5, lane = tid & 31;
    int m0 = (wid >> 1)*32;
    int n0 = (wid & 1)*(NB/2);
    int lrow = lane & 7, lq8 = (lane >> 3) & 1, lkhi = lane >> 4;

    float acc[2][NCC][2][4];
    #pragma unroll
    for (int mi = 0; mi < 2; mi++)
        #pragma unroll
        for (int nc = 0; nc < NCC; nc++)
            #pragma unroll
            for (int sb = 0; sb < 2; sb++)
                #pragma unroll
                for (int q = 0; q < 4; q++) acc[mi][nc][sb][q] = 0.f;

    // stage 0 prefetch
    {
        unsigned base = smem_base;
        #pragma unroll
        for (int it = 0; it < TOTAL/256; it++){
            int idx = tid + it*256;
            const __nv_bfloat16* src; unsigned sec; int row, col;
            if (idx < 1024){ row = idx >> 3; col = idx & 7; src = L + (size_t)row*CC + col*8; sec = 0; }
            else { int i2 = idx - 1024; row = i2 >> 3; col = i2 & 7; src = Bsrc + (size_t)row*CC + col*8; sec = 16384; }
            unsigned boff = row*128 + col*16;
            cp16(base + sec + (boff ^ ((boff >> 3) & 0x70)), src);
        }
        asm volatile("cp.async.commit_group;" ::: "memory");
    }

    for (int s = 0; s < 16; s++){
        int buf = s & 1;
        if (s + 1 < 16){
            int k0 = (s+1)*64;
            unsigned base = smem_base + (buf^1)*BUFSZ;
            #pragma unroll
            for (int it = 0; it < TOTAL/256; it++){
                int idx = tid + it*256;
                const __nv_bfloat16* src; unsigned sec; int row, col;
                if (idx < 1024){ row = idx >> 3; col = idx & 7; src = L + (size_t)row*CC + k0 + col*8; sec = 0; }
                else { int i2 = idx - 1024; row = i2 >> 3; col = i2 & 7; src = Bsrc + (size_t)row*CC + k0 + col*8; sec = 16384; }
                unsigned boff = row*128 + col*16;
                cp16(base + sec + (boff ^ ((boff >> 3) & 0x70)), src);
            }
            asm volatile("cp.async.commit_group;" ::: "memory");
            asm volatile("cp.async.wait_group 1;" ::: "memory");
        } else {
            asm volatile("cp.async.wait_group 0;" ::: "memory");
        }
        __syncthreads();

        unsigned ab = smem_base + buf*BUFSZ;
        #pragma unroll
        for (int kk = 0; kk < 4; kk++){
            unsigned a[2][4];
            #pragma unroll
            for (int mi = 0; mi < 2; mi++){
                unsigned row = m0 + mi*16 + lrow + lq8*8;
                unsigned boff = row*128 + kk*32 + lkhi*16;
                unsigned sw = boff ^ ((boff >> 3) & 0x70);
                ldsm4(a[mi][0], a[mi][1], a[mi][2], a[mi][3], ab + sw);
            }
            #pragma unroll
            for (int nc = 0; nc < NCC; nc++){
                unsigned row = n0 + nc*16 + lrow + lq8*8;
                unsigned boff = row*128 + kk*32 + lkhi*16;
                unsigned sw = boff ^ ((boff >> 3) & 0x70);
                unsigned bh[4];
                ldsm4(bh[0], bh[1], bh[2], bh[3], ab + 16384 + sw);
                #pragma unroll
                for (int mi = 0; mi < 2; mi++){
                    mma16816(acc[mi][nc][0], a[mi], bh[0], bh[2]);
                    mma16816(acc[mi][nc][1], a[mi], bh[1], bh[3]);
                }
            }
        }
        __syncthreads();
    }

    int g = lane >> 2, cpair = (lane & 3)*2;
    #pragma unroll
    for (int mi = 0; mi < 2; mi++){
        int row = m0 + mi*16 + g;
        #pragma unroll
        for (int nc = 0; nc < NCC; nc++){
            #pragma unroll
            for (int sb = 0; sb < 2; sb++){
                int col = n0 + nc*16 + sb*8 + cpair;
                float* cc = acc[mi][nc][sb];
                *(__nv_bfloat162*)(Zdst + (size_t)row*ldz + col) =
                    __floats2bfloat162_rn(cc[0], cc[1]);
                *(__nv_bfloat162*)(Zdst + (size_t)(row+8)*ldz + col) =
                    __floats2bfloat162_rn(cc[2], cc[3]);
            }
        }
    }
}

// ================ generic bf16 HMMA GEMM (task table) ================
#define SG_BUFSZ 40960
#define SG_SMEM  (2*SG_BUFSZ)

__global__ void __launch_bounds__(256) sgemm_kernel(int basecfg){
    int which = basecfg + blockIdx.y;
    const __nv_bfloat16 *A, *W;
    int lda, K, N, ldc, act = 0;
    const float* bias;
    float* Cf = nullptr;
    __nv_bfloat16 *Cbf = nullptr;

    switch (which){
    case 0: A=g_Zhf; lda=128; K=128; W=g_Wfwd; N=128; bias=g_bias+OFF_FWD;
            Cbf=g_gcat; ldc=256; act=1; break;
    case 1: A=g_Zhb; lda=128; K=128; W=g_Wbwd; N=128; bias=g_bias+OFF_BWD;
            Cbf=g_gcat+128; ldc=256; act=1; break;
    case 2: A=g_gcat; lda=256; K=256; W=g_Wmerge; N=128; bias=g_bias+OFF_MERGE;
            Cf=g_hsf; Cbf=g_hsb; ldc=128; break;
    case 3: case 4: {
        int j = which - 3;
        A=g_hsb; lda=128; K=128; W=g_Whh + j*192*128; N=192; bias=g_bias+OFF_BHH+j*192;
        Cf=g_gh + j*192; ldc=384; break; }
    case 5: A=g_Zxf; lda=64; K=64; W=g_WfeF; N=32; bias=g_bias+OFF_FEF;
            Cbf=g_tmp; ldc=64; act=1; break;
    case 6: A=g_Zxb; lda=64; K=64; W=g_WfeB; N=32; bias=g_bias+OFF_FEB;
            Cbf=g_tmp+32; ldc=64; act=1; break;
    case 7: case 8: {
        int j = which - 7;
        A=g_tmp; lda=64; K=64; W=g_Wih + j*192*64; N=192; bias=g_bias+OFF_BIH+j*192;
        Cf=g_gi_all + j*192; ldc=384; break; }
    default: // 9: init
        A=g_Zxf; lda=64; K=64; W=g_Winit; N=128; bias=g_bias+OFF_INIT;
        Cf=g_h; ldc=128; act=1; break;
    }

    extern __shared__ char smem[];
    unsigned smem_base = smem_u32(smem);
    int tid = threadIdx.x;
    int mtile = blockIdx.x;
    int wid = tid >> 5, lane = tid & 31;
    int m0 = (wid >> 1)*32;
    int Nw = N >> 1;
    int n0 = (wid & 1)*Nw;
    int ncCount = Nw >> 4; if (ncCount < 1) ncCount = 1;
    int lrow = lane & 7, lq8 = (lane >> 3) & 1, lkhi = lane >> 4;
    int nstages = K >> 6;

    float acc[2][6][2][4];
    #pragma unroll
    for (int mi = 0; mi < 2; mi++)
        #pragma unroll
        for (int nc = 0; nc < 6; nc++)
            #pragma unroll
            for (int sb = 0; sb < 2; sb++)
                #pragma unroll
                for (int q = 0; q < 4; q++) acc[mi][nc][sb][q] = 0.f;

    int total = 1024 + N*8;
    // stage 0
    for (int idx = tid; idx < total; idx += 256){
        const __nv_bfloat16* src; unsigned sec; int row, col;
        if (idx < 1024){ row = idx >> 3; col = idx & 7;
            src = A + ((size_t)mtile*128 + row)*lda + col*8; sec = 0; }
        else { int i2 = idx - 1024; row = i2 >> 3; col = i2 & 7;
            src = W + (size_t)row*K + col*8; sec = 16384; }
        unsigned boff = row*128 + col*16;
        cp16(smem_base + sec + (boff ^ ((boff >> 3) & 0x70)), src);
    }
    asm volatile("cp.async.commit_group;" ::: "memory");

    for (int s = 0; s < nstages; s++){
        int buf = s & 1;
        if (s + 1 < nstages){
            int k0 = (s+1)*64;
            unsigned base = smem_base + (buf^1)*SG_BUFSZ;
            for (int idx = tid; idx < total; idx += 256){
                const __nv_bfloat16* src; unsigned sec; int row, col;
                if (idx < 1024){ row = idx >> 3; col = idx & 7;
                    src = A + ((size_t)mtile*128 + row)*lda + k0 + col*8; sec = 0; }
                else { int i2 = idx - 1024; row = i2 >> 3; col = i2 & 7;
                    src = W + (size_t)row*K + k0 + col*8; sec = 16384; }
                unsigned boff = row*128 + col*16;
                cp16(base + sec + (boff ^ ((boff >> 3) & 0x70)), src);
            }
            asm volatile("cp.async.commit_group;" ::: "memory");
            asm volatile("cp.async.wait_group 1;" ::: "memory");
        } else {
            asm volatile("cp.async.wait_group 0;" ::: "memory");
        }
        __syncthreads();

        unsigned ab = smem_base + buf*SG_BUFSZ;
        #pragma unroll
        for (int kk = 0; kk < 4; kk++){
            unsigned a[2][4];
            #pragma unroll
            for (int mi = 0; mi < 2; mi++){
                unsigned row = m0 + mi*16 + lrow + lq8*8;
                unsigned boff = row*128 + kk*32 + lkhi*16;
                unsigned sw = boff ^ ((boff >> 3) & 0x70);
                ldsm4(a[mi][0], a[mi][1], a[mi][2], a[mi][3], ab + sw);
            }
            for (int nc = 0; nc < ncCount; nc++){
                unsigned row = n0 + nc*16 + lrow + lq8*8;
                unsigned boff = row*128 + kk*32 + lkhi*16;
                unsigned sw = boff ^ ((boff >> 3) & 0x70);
                unsigned bh[4];
                ldsm4(bh[0], bh[1], bh[2], bh[3], ab + 16384 + sw);
                #pragma unroll
                for (int mi = 0; mi < 2; mi++){
                    mma16816(acc[mi][nc][0], a[mi], bh[0], bh[2]);
                    mma16816(acc[mi][nc][1], a[mi], bh[1], bh[3]);
                }
            }
        }
        __syncthreads();
    }

    int g = lane >> 2, cpair = (lane & 3)*2;
    #pragma unroll
    for (int mi = 0; mi < 2; mi++){
        int row = mtile*128 + m0 + mi*16 + g;
        for (int nc = 0; nc < ncCount; nc++){
            #pragma unroll
            for (int sb = 0; sb < 2; sb++){
                int col = n0 + nc*16 + sb*8 + cpair;
                float b0 = bias[col], b1 = bias[col+1];
                float* cc = acc[mi][nc][sb];
                float v00 = cc[0] + b0, v01 = cc[1] + b1;
                float v10 = cc[2] + b0, v11 = cc[3] + b1;
                if (act){
                    v00 = fmaxf(v00, 0.f); v01 = fmaxf(v01, 0.f);
                    v10 = fmaxf(v10, 0.f); v11 = fmaxf(v11, 0.f);
                }
                if (Cf){
                    *(float2*)(Cf + (size_t)row*ldc + col)     = make_float2(v00, v01);
                    *(float2*)(Cf + (size_t)(row+8)*ldc + col) = make_float2(v10, v11);
                }
                if (Cbf){
                    *(__nv_bfloat162*)(Cbf + (size_t)row*ldc + col)     = __floats2bfloat162_rn(v00, v01);
                    *(__nv_bfloat162*)(Cbf + (size_t)(row+8)*ldc + col) = __floats2bfloat162_rn(v10, v11);
                }
            }
        }
    }
}

// ---------------- fused GRU gates + h transpose/split + history ----------------
__global__ void gru_tr_kernel(int t){
    __shared__ float tile[32][33];
    int c0 = blockIdx.x*32, f0 = blockIdx.y*32;
    int b = blockIdx.z;
    int tx = threadIdx.x, ty = threadIdx.y;   // tx = f local (coalesced), ty = c local /8
    #pragma unroll
    for (int r = 0; r < 4; r++){
        int cl = ty + r*8;
        size_t row = (size_t)b*CC + c0 + cl;
        int f = f0 + tx;
        const float* gi = g_gi_all + ((size_t)t*ROWS + row)*384;
        const float* gh = g_gh + row*384;
        float ir = gi[f], iz = gi[128 + f], inn = gi[256 + f];
        float hr = gh[f], hz = gh[128 + f], hn  = gh[256 + f];
        float rg = 1.f / (1.f + expf(-(ir + hr)));
        float zg = 1.f / (1.f + expf(-(iz + hz)));
        float ng = tanhf(inn + rg*hn);
        float hs = g_hsf[row*HH + f];
        float h = (1.f - zg)*ng + zg*hs;
        tile[cl][tx] = h;
        if (t >= 4) g_hist[((size_t)(t-4)*ROWS + row)*HH + f] = h;
    }
    __syncthreads();
    #pragma unroll
    for (int r = 0; r < 4; r++){
        int fl = ty + r*8;
        int f = f0 + fl, c = c0 + tx;
        g_BH[((size_t)b*HH + f)*CC + c] = __float2bfloat16(tile[tx][fl]);
    }
}

// ---------------- final: pred = hist @ outW + outb, fused mask-scatter ----------------
__global__ void __launch_bounds__(256) predout_kernel(const float* __restrict__ in,
                                                      const float* __restrict__ outW,
                                                      const float* __restrict__ outb,
                                                      float* __restrict__ out){
    __shared__ float Ws[128*32];
    __shared__ float As[64*128];
    int r0 = blockIdx.x*64;
    int tid = threadIdx.x;
    for (int i = tid; i < 128*32; i += 256) Ws[i] = outW[i];
    {
        const float4* src = (const float4*)(g_hist + (size_t)r0*HH);
        float4* dst = (float4*)As;
        for (int i = tid; i < 64*128/4; i += 256) dst[i] = src[i];
    }
    __syncthreads();

    #pragma unroll
    for (int it = 0; it < 2; it++){
        int item = tid + it*256;          // 512 items: 64 rows x 8 col-groups
        int rl = item >> 3;
        int cg = (item & 7)*4;
        float a0 = outb[cg], a1 = outb[cg+1], a2 = outb[cg+2], a3 = outb[cg+3];
        const float* Ar = As + rl*128;
        #pragma unroll 8
        for (int k = 0; k < 128; k++){
            float av = Ar[k];
            const float* wr = Ws + k*32 + cg;
            a0 += av*wr[0]; a1 += av*wr[1]; a2 += av*wr[2]; a3 += av*wr[3];
        }
        int r = r0 + rl;
        int t = r >> 13;                  // slot 0..26
        int rb = r & 8191;
        int b = rb >> 10, c = rb & 1023;
        float4 v;
        if (g_mask[c])
            v = *(const float4*)(in + (((size_t)(b*TT + t + 5)*CC + c)*160) + cg);
        else
            v = make_float4(a0, a1, a2, a3);
        *(float4*)(out + (((size_t)(b*SS + t)*CC + c)*DST) + cg) = v;
    }
}

// ---------------- host orchestration ----------------
static __nv_bfloat16* symb(const void* s){ void* p = nullptr; cudaGetSymbolAddress(&p, s); return (__nv_bfloat16*)p; }

extern "C" void kernel_launch(void* const* d_in, const int* in_sizes, int n_in,
                              void* d_out, int out_size)
{
    const float* inputs   = (const float*)d_in[0];
    const float* adj      = (const float*)d_in[1];
    const float* init_W   = (const float*)d_in[2];
    const float* init_b   = (const float*)d_in[3];
    const float* fe_fwd_W = (const float*)d_in[4];
    const float* fe_fwd_b = (const float*)d_in[5];
    const float* fe_bwd_W = (const float*)d_in[6];
    const float* fe_bwd_b = (const float*)d_in[7];
    const float* fwd_W    = (const float*)d_in[8];
    const float* fwd_b    = (const float*)d_in[9];
    const float* bwd_W    = (const float*)d_in[10];
    const float* bwd_b    = (const float*)d_in[11];
    const float* merge_W  = (const float*)d_in[12];
    const float* merge_b  = (const float*)d_in[13];
    const float* gru_Wih  = (const float*)d_in[14];
    const float* gru_bih  = (const float*)d_in[15];
    const float* gru_Whh  = (const float*)d_in[16];
    const float* gru_bhh  = (const float*)d_in[17];
    const float* out_W    = (const float*)d_in[18];
    const float* out_b    = (const float*)d_in[19];
    const int*   cells    = (const int*)  d_in[20];
    float* out = (float*)d_out;

    const int PROP_X_SMEM = 2*(16384 + 64*128);   // 49152
    const int PROP_H_SMEM = 2*(16384 + 128*128);  // 65536
    cudaFuncSetAttribute(prop_kernel<64,0>,  cudaFuncAttributeMaxDynamicSharedMemorySize, PROP_X_SMEM);
    cudaFuncSetAttribute(prop_kernel<128,1>, cudaFuncAttributeMaxDynamicSharedMemorySize, PROP_H_SMEM);
    cudaFuncSetAttribute(sgemm_kernel,       cudaFuncAttributeMaxDynamicSharedMemorySize, SG_SMEM);

    // ---- prolog ----
    rowsum_kernel<<<TT*CC/8, 256>>>(adj);
    colsum_kernel<<<dim3(4, TT), 256>>>(adj);
    build_L_kernel<<<dim3(CC/32, CC/32, TT), dim3(32, 8)>>>(adj);
    build_BX_kernel<<<dim3(CC/32, FIN/32, BB*TT), dim3(32, 8)>>>(inputs);
    mask_init_kernel<<<4, 256>>>();
    int nic = in_sizes[20];
    mask_set_kernel<<<(nic + 255)/256, 256>>>(cells, nic);

    wconv_kernel<<<(128*64 + 255)/256, 256>>>(init_W,  symb(g_Winit), 64, 128);
    wconv_kernel<<<(32*64 + 255)/256, 256>>>(fe_fwd_W, symb(g_WfeF),  64, 32);
    wconv_kernel<<<(32*64 + 255)/256, 256>>>(fe_bwd_W, symb(g_WfeB),  64, 32);
    wconv_kernel<<<(128*128 + 255)/256, 256>>>(fwd_W,  symb(g_Wfwd),  128, 128);
    wconv_kernel<<<(128*128 + 255)/256, 256>>>(bwd_W,  symb(g_Wbwd),  128, 128);
    wconv_kernel<<<(128*256 + 255)/256, 256>>>(merge_W,symb(g_Wmerge),256, 128);
    wconv_kernel<<<(384*64 + 255)/256, 256>>>(gru_Wih, symb(g_Wih),   64, 384);
    wconv_kernel<<<(384*128 + 255)/256, 256>>>(gru_Whh,symb(g_Whh),   128, 384);
    bias_copy_kernel<<<2, 256>>>(init_b, fe_fwd_b, fe_bwd_b, fwd_b, bwd_b, merge_b,
                                 gru_bih, gru_bhh);

    // ---- x-dependent precompute (no recurrence) ----
    prop_kernel<64,0><<<dim3(BB, 8, NT*2), 256, PROP_X_SMEM>>>(0);  // Zx all t, both dirs
    sgemm_kernel<<<dim3(NT*64, 2), 256, SG_SMEM>>>(5);              // fe fwd+bwd -> tmp (all t)
    sgemm_kernel<<<dim3(NT*64, 2), 256, SG_SMEM>>>(7);              // gi (all t)
    sgemm_kernel<<<dim3(64, 1), 256, SG_SMEM>>>(9);                 // hidden0 -> g_h
    transpose_h_kernel<<<dim3(CC/32, HH/32, BB), dim3(32, 8)>>>();  // h -> BH

    // ---- scan (recurrent part only) ----
    for (int t = 0; t < NT; t++){
        prop_kernel<128,1><<<dim3(BB, 16), 256, PROP_H_SMEM>>>(t);  // Zh = L @ h
        sgemm_kernel<<<dim3(64, 2), 256, SG_SMEM>>>(0);             // fwd, bwd -> gcat
        sgemm_kernel<<<dim3(64, 1), 256, SG_SMEM>>>(2);             // merge -> hs (f32 + bf16)
        sgemm_kernel<<<dim3(64, 2), 256, SG_SMEM>>>(3);             // gh
        gru_tr_kernel<<<dim3(32, 4, BB), dim3(32, 8)>>>(t);         // h update + BH + hist
    }

    // ---- output ----
    predout_kernel<<<SS*ROWS/64, 256>>>(inputs, out_W, out_b, out);
}